// round 1
// baseline (speedup 1.0000x reference)
#include <cuda_runtime.h>
#include <math.h>

#define NROWS 131072
#define DIM 64
#define KC 64
#define TILE 64
#define NTILES 2048          // NROWS / TILE
#define NBLK 512
#define TPB 256
#define ITERS 10
#define LDP 68               // padded stride (floats) for conflict-free smem

// ---------------- device globals (no cudaMalloc allowed) ----------------
__device__ float g_clusters[KC * DIM];
__device__ float g_S[KC * LDP];              // reduced sums: [k*LDP+d], d==64 -> colsum
__device__ float g_part[NBLK][KC * LDP];     // per-block partials
__device__ float g_wsq[NROWS];
__device__ int   g_done;

// ---------------- init: done flag, cluster copy, ||w||^2 ----------------
__global__ void init_kernel(const float* __restrict__ W, const float* __restrict__ C0) {
    int gid = blockIdx.x * blockDim.x + threadIdx.x;   // grid == NROWS threads exactly
    if (gid == 0) g_done = 0;
    if (gid < KC * DIM) g_clusters[gid] = C0[gid];
    const float4* p = (const float4*)(W + (size_t)gid * DIM);
    float s = 0.f;
#pragma unroll
    for (int j = 0; j < 16; j++) {
        float4 v = p[j];
        s += v.x * v.x + v.y * v.y + v.z * v.z + v.w * v.w;
    }
    g_wsq[gid] = s;
}

// ---------------- fused iteration kernel ----------------
// Per 64-row tile: d2 = ||w||^2 + ||c||^2 - 2 W C^T  -> softmax(-sqrt(d2)) ->
// write attn to gmem, accumulate attn^T W (+colsum) into per-block registers.
__global__ __launch_bounds__(TPB, 3) void iter_kernel(const float* __restrict__ W,
                                                      float* __restrict__ attn_out) {
    if (g_done) return;
    extern __shared__ float sm[];
    float* csT  = sm;                      // [64][LDP]  clusters transposed: csT[d*LDP+k]
    float* wsT  = sm + 64 * LDP;           // [64][LDP]  W tile transposed:  wsT[d*LDP+r]
    float* wrow = sm + 2 * 64 * LDP;       // [64][64]   W tile row-major
    float* att  = sm + 2 * 64 * LDP + 64 * 64;  // [64][LDP] d2 then attn
    float* csq  = att + 64 * LDP;          // [64]
    float* wsq  = csq + 64;                // [64]

    const int tid = threadIdx.x;
    const int tx = tid & 15, ty = tid >> 4;
    const int i0 = ty * 4, k0 = tx * 4;

    // load + transpose clusters (persistent for this kernel)
    for (int i = tid; i < KC * DIM; i += TPB) {
        float v = g_clusters[i];
        csT[(i & 63) * LDP + (i >> 6)] = v;
    }
    __syncthreads();
    if (tid < KC) {
        float s = 0.f;
#pragma unroll
        for (int d = 0; d < DIM; d++) { float v = csT[d * LDP + tid]; s += v * v; }
        csq[tid] = s;
    }

    float c2[4][4];
#pragma unroll
    for (int a = 0; a < 4; a++)
#pragma unroll
        for (int b = 0; b < 4; b++) c2[a][b] = 0.f;
    float csum[4] = {0.f, 0.f, 0.f, 0.f};

    for (int tile = blockIdx.x; tile < NTILES; tile += NBLK) {
        const int row0 = tile * TILE;
        __syncthreads();   // prev GEMM2 done (and csq ready on first pass)

        // load W tile into both layouts
        for (int i = tid * 4; i < TILE * DIM; i += TPB * 4) {
            float4 v = *(const float4*)(W + (size_t)row0 * DIM + i);
            int r = i >> 6, d = i & 63;
            *(float4*)(wrow + r * 64 + d) = v;
            wsT[(d + 0) * LDP + r] = v.x;
            wsT[(d + 1) * LDP + r] = v.y;
            wsT[(d + 2) * LDP + r] = v.z;
            wsT[(d + 3) * LDP + r] = v.w;
        }
        if (tid < TILE) wsq[tid] = g_wsq[row0 + tid];
        __syncthreads();

        // GEMM1: acc[ii][kk] = dot(w_{i0+ii}, c_{k0+kk})
        float acc[4][4];
#pragma unroll
        for (int a = 0; a < 4; a++)
#pragma unroll
            for (int b = 0; b < 4; b++) acc[a][b] = 0.f;
#pragma unroll 8
        for (int d = 0; d < DIM; d++) {
            float4 av = *(float4*)(wsT + d * LDP + i0);
            float4 bv = *(float4*)(csT + d * LDP + k0);
            float a[4] = {av.x, av.y, av.z, av.w};
            float b[4] = {bv.x, bv.y, bv.z, bv.w};
#pragma unroll
            for (int ii = 0; ii < 4; ii++)
#pragma unroll
                for (int kk = 0; kk < 4; kk++)
                    acc[ii][kk] += a[ii] * b[kk];
        }
        // d2 -> smem
#pragma unroll
        for (int ii = 0; ii < 4; ii++) {
            float w2 = wsq[i0 + ii];
            float4 v;
            v.x = w2 + csq[k0 + 0] - 2.f * acc[ii][0];
            v.y = w2 + csq[k0 + 1] - 2.f * acc[ii][1];
            v.z = w2 + csq[k0 + 2] - 2.f * acc[ii][2];
            v.w = w2 + csq[k0 + 3] - 2.f * acc[ii][3];
            *(float4*)(att + (i0 + ii) * LDP + k0) = v;
        }
        __syncthreads();

        // softmax(-sqrt(d2)) per row; 4 threads/row, 16 cols each
        {
            const int row = tid >> 2, q = tid & 3;
            float e[16];
            float mn = 3.4e38f;
#pragma unroll
            for (int j = 0; j < 16; j++) {
                float d2v = att[row * LDP + q * 16 + j];
                float dv = sqrtf(fmaxf(d2v, 0.f));
                e[j] = dv;
                mn = fminf(mn, dv);
            }
            mn = fminf(mn, __shfl_xor_sync(0xffffffffu, mn, 1));
            mn = fminf(mn, __shfl_xor_sync(0xffffffffu, mn, 2));
            float s = 0.f;
#pragma unroll
            for (int j = 0; j < 16; j++) {
                float ex = __expf(mn - e[j]);   // exp((min_dist - dist)/T), T=1
                e[j] = ex;
                s += ex;
            }
            s += __shfl_xor_sync(0xffffffffu, s, 1);
            s += __shfl_xor_sync(0xffffffffu, s, 2);
            float inv = 1.f / s;
            float* ga = attn_out + (size_t)(row0 + row) * KC + q * 16;
#pragma unroll
            for (int j4 = 0; j4 < 4; j4++) {
                float4 v;
                v.x = e[j4 * 4 + 0] * inv; v.y = e[j4 * 4 + 1] * inv;
                v.z = e[j4 * 4 + 2] * inv; v.w = e[j4 * 4 + 3] * inv;
                *(float4*)(att + row * LDP + q * 16 + j4 * 4) = v;
                *(float4*)(ga + j4 * 4) = v;
            }
        }
        __syncthreads();

        // GEMM2: c2[kk][dd] += sum_r attn[r][k0+kk] * W[r][i0+dd]  (i0 plays d0)
#pragma unroll 8
        for (int r = 0; r < TILE; r++) {
            float4 av = *(float4*)(att + r * LDP + k0);
            float4 bv = *(float4*)(wrow + r * 64 + i0);
            float a[4] = {av.x, av.y, av.z, av.w};
            float b[4] = {bv.x, bv.y, bv.z, bv.w};
#pragma unroll
            for (int kk = 0; kk < 4; kk++)
#pragma unroll
                for (int dd = 0; dd < 4; dd++)
                    c2[kk][dd] += a[kk] * b[dd];
            if (ty == 0) {   // one d-stripe accumulates colsum
                csum[0] += a[0]; csum[1] += a[1]; csum[2] += a[2]; csum[3] += a[3];
            }
        }
    }

    // write per-block partials (deterministic two-stage reduction, no atomics)
    float* P = g_part[blockIdx.x];
#pragma unroll
    for (int kk = 0; kk < 4; kk++) {
        float4 v = {c2[kk][0], c2[kk][1], c2[kk][2], c2[kk][3]};
        *(float4*)(P + (k0 + kk) * LDP + i0) = v;
    }
    if (ty == 0) {
#pragma unroll
        for (int kk = 0; kk < 4; kk++) P[(k0 + kk) * LDP + 64] = csum[kk];
    }
}

// ---------------- stage-2 reduction of partials ----------------
__global__ void reduce_kernel() {
    if (g_done) return;
    int idx = blockIdx.x * blockDim.x + threadIdx.x;
    if (idx >= KC * 65) return;
    int k = idx / 65, d = idx % 65;
    float s = 0.f;
    for (int b = 0; b < NBLK; b += 4) {
        s += g_part[b + 0][k * LDP + d] + g_part[b + 1][k * LDP + d]
           + g_part[b + 2][k * LDP + d] + g_part[b + 3][k * LDP + d];
    }
    g_S[k * LDP + d] = s;
}

// ---------------- cluster update + convergence (single block) ----------------
__global__ void update_kernel() {
    if (g_done) return;
    __shared__ float red[8];
    __shared__ int s_conv;
    int tid = threadIdx.x;
    float newv[16];
    float dsum = 0.f;
#pragma unroll
    for (int j = 0; j < 16; j++) {
        int idx = j * 256 + tid;
        int k = idx >> 6;
        float nv = g_S[k * LDP + (idx & 63)] / g_S[k * LDP + 64];
        newv[j] = nv;
        float diff = nv - g_clusters[idx];
        dsum += diff * diff;
    }
#pragma unroll
    for (int o = 16; o > 0; o >>= 1) dsum += __shfl_xor_sync(0xffffffffu, dsum, o);
    if ((tid & 31) == 0) red[tid >> 5] = dsum;
    __syncthreads();
    if (tid == 0) {
        float t = 0.f;
        for (int w = 0; w < 8; w++) t += red[w];
        s_conv = (sqrtf(t) <= 1e-4f) ? 1 : 0;   // Frobenius norm <= EPSILON
        if (s_conv) g_done = 1;                 // freeze: clusters NOT updated
    }
    __syncthreads();
    if (!s_conv) {
#pragma unroll
        for (int j = 0; j < 16; j++) g_clusters[j * 256 + tid] = newv[j];
    }
}

// ---------------- final: compressed = attn @ clusters; emit clusters ----------------
__global__ __launch_bounds__(TPB) void final_kernel(const float* __restrict__ attn,
                                                    float* __restrict__ comp,
                                                    float* __restrict__ clus_out) {
    __shared__ float cs[KC * DIM];   // clusters row-major [k][d]
    __shared__ float aT[KC * LDP];   // attn tile transposed [k][row]
    int tid = threadIdx.x;
    for (int i = tid; i < KC * DIM; i += TPB) {
        float v = g_clusters[i];
        cs[i] = v;
        if (blockIdx.x == 0) clus_out[i] = v;
    }
    size_t row0 = (size_t)blockIdx.x * TILE;
    for (int i = tid * 4; i < TILE * KC; i += TPB * 4) {
        float4 v = *(const float4*)(attn + row0 * KC + i);
        int r = i >> 6, k = i & 63;
        aT[(k + 0) * LDP + r] = v.x;
        aT[(k + 1) * LDP + r] = v.y;
        aT[(k + 2) * LDP + r] = v.z;
        aT[(k + 3) * LDP + r] = v.w;
    }
    __syncthreads();
    int tx = tid & 15, ty = tid >> 4;
    int i0 = ty * 4, d0 = tx * 4;
    float acc[4][4];
#pragma unroll
    for (int a = 0; a < 4; a++)
#pragma unroll
        for (int b = 0; b < 4; b++) acc[a][b] = 0.f;
#pragma unroll 8
    for (int k = 0; k < KC; k++) {
        float4 av = *(float4*)(aT + k * LDP + i0);
        float4 bv = *(float4*)(cs + k * 64 + d0);
        float a[4] = {av.x, av.y, av.z, av.w};
        float b[4] = {bv.x, bv.y, bv.z, bv.w};
#pragma unroll
        for (int ii = 0; ii < 4; ii++)
#pragma unroll
            for (int dd = 0; dd < 4; dd++)
                acc[ii][dd] += a[ii] * b[dd];
    }
#pragma unroll
    for (int ii = 0; ii < 4; ii++) {
        float4 v = {acc[ii][0], acc[ii][1], acc[ii][2], acc[ii][3]};
        *(float4*)(comp + (row0 + i0 + ii) * DIM + d0) = v;
    }
}

// ---------------- launch ----------------
extern "C" void kernel_launch(void* const* d_in, const int* in_sizes, int n_in,
                              void* d_out, int out_size) {
    const float* W  = (const float*)d_in[0];
    const float* C0 = (const float*)d_in[1];
    float* out  = (float*)d_out;
    float* comp = out;                                    // [N, D]
    float* clus = out + (size_t)NROWS * DIM;              // [K, D]
    float* attn = clus + (size_t)KC * DIM;                // [N, K]

    size_t smem = (size_t)(3 * 64 * LDP + 64 * 64 + 128) * sizeof(float);  // 69120 B
    cudaFuncSetAttribute(iter_kernel, cudaFuncAttributeMaxDynamicSharedMemorySize, (int)smem);

    init_kernel<<<NROWS / TPB, TPB>>>(W, C0);
    for (int it = 0; it < ITERS; it++) {
        iter_kernel<<<NBLK, TPB, smem>>>(W, attn);
        reduce_kernel<<<(KC * 65 + TPB - 1) / TPB, TPB>>>();
        update_kernel<<<1, TPB>>>();
    }
    final_kernel<<<NTILES, TPB>>>(attn, comp, clus);
}

// round 2
// speedup vs baseline: 1.0019x; 1.0019x over previous
#include <cuda_runtime.h>
#include <math.h>

#define NROWS 131072
#define DIM 64
#define KC 64
#define TILE 64
#define NTILES 2048          // NROWS / TILE
#define NBLK 512
#define TPB 256
#define ITERS 10
#define LDP 68               // padded stride (floats) for conflict-free smem

// ---------------- device globals (no cudaMalloc allowed) ----------------
__device__ float g_clusters[KC * DIM];
__device__ float g_S[KC * LDP];              // reduced sums: [k*LDP+d], d==64 -> colsum
__device__ float g_part[NBLK][KC * LDP];     // per-block partials
__device__ float g_wsq[NROWS];
__device__ int   g_done;

// ---------------- init: done flag, cluster copy, ||w||^2 ----------------
__global__ void init_kernel(const float* __restrict__ W, const float* __restrict__ C0) {
    int gid = blockIdx.x * blockDim.x + threadIdx.x;   // grid == NROWS threads exactly
    if (gid == 0) g_done = 0;
    if (gid < KC * DIM) g_clusters[gid] = C0[gid];
    const float4* p = (const float4*)(W + (size_t)gid * DIM);
    float s = 0.f;
#pragma unroll
    for (int j = 0; j < 16; j++) {
        float4 v = p[j];
        s += v.x * v.x + v.y * v.y + v.z * v.z + v.w * v.w;
    }
    g_wsq[gid] = s;
}

// ---------------- fused iteration kernel ----------------
// Per 64-row tile: d2 = ||w||^2 + ||c||^2 - 2 W C^T  -> softmax(-sqrt(d2)) ->
// write attn to gmem, accumulate attn^T W (+colsum) into per-block registers.
__global__ __launch_bounds__(TPB, 3) void iter_kernel(const float* __restrict__ W,
                                                      float* __restrict__ attn_out) {
    if (g_done) return;
    extern __shared__ float sm[];
    float* csT  = sm;                      // [64][LDP]  clusters transposed: csT[d*LDP+k]
    float* wsT  = sm + 64 * LDP;           // [64][LDP]  W tile transposed:  wsT[d*LDP+r]
    float* wrow = sm + 2 * 64 * LDP;       // [64][64]   W tile row-major
    float* att  = sm + 2 * 64 * LDP + 64 * 64;  // [64][LDP] d2 then attn
    float* csq  = att + 64 * LDP;          // [64]
    float* wsq  = csq + 64;                // [64]

    const int tid = threadIdx.x;
    const int tx = tid & 15, ty = tid >> 4;
    const int i0 = ty * 4, k0 = tx * 4;

    // load + transpose clusters (persistent for this kernel)
    for (int i = tid; i < KC * DIM; i += TPB) {
        float v = g_clusters[i];
        csT[(i & 63) * LDP + (i >> 6)] = v;
    }
    __syncthreads();
    if (tid < KC) {
        float s = 0.f;
#pragma unroll
        for (int d = 0; d < DIM; d++) { float v = csT[d * LDP + tid]; s += v * v; }
        csq[tid] = s;
    }

    float c2[4][4];
#pragma unroll
    for (int a = 0; a < 4; a++)
#pragma unroll
        for (int b = 0; b < 4; b++) c2[a][b] = 0.f;
    float csum[4] = {0.f, 0.f, 0.f, 0.f};

    for (int tile = blockIdx.x; tile < NTILES; tile += NBLK) {
        const int row0 = tile * TILE;
        __syncthreads();   // prev GEMM2 done (and csq ready on first pass)

        // load W tile into both layouts
        for (int i = tid * 4; i < TILE * DIM; i += TPB * 4) {
            float4 v = *(const float4*)(W + (size_t)row0 * DIM + i);
            int r = i >> 6, d = i & 63;
            *(float4*)(wrow + r * 64 + d) = v;
            wsT[(d + 0) * LDP + r] = v.x;
            wsT[(d + 1) * LDP + r] = v.y;
            wsT[(d + 2) * LDP + r] = v.z;
            wsT[(d + 3) * LDP + r] = v.w;
        }
        if (tid < TILE) wsq[tid] = g_wsq[row0 + tid];
        __syncthreads();

        // GEMM1: acc[ii][kk] = dot(w_{i0+ii}, c_{k0+kk})
        float acc[4][4];
#pragma unroll
        for (int a = 0; a < 4; a++)
#pragma unroll
            for (int b = 0; b < 4; b++) acc[a][b] = 0.f;
#pragma unroll 8
        for (int d = 0; d < DIM; d++) {
            float4 av = *(float4*)(wsT + d * LDP + i0);
            float4 bv = *(float4*)(csT + d * LDP + k0);
            float a[4] = {av.x, av.y, av.z, av.w};
            float b[4] = {bv.x, bv.y, bv.z, bv.w};
#pragma unroll
            for (int ii = 0; ii < 4; ii++)
#pragma unroll
                for (int kk = 0; kk < 4; kk++)
                    acc[ii][kk] += a[ii] * b[kk];
        }
        // d2 -> smem
#pragma unroll
        for (int ii = 0; ii < 4; ii++) {
            float w2 = wsq[i0 + ii];
            float4 v;
            v.x = w2 + csq[k0 + 0] - 2.f * acc[ii][0];
            v.y = w2 + csq[k0 + 1] - 2.f * acc[ii][1];
            v.z = w2 + csq[k0 + 2] - 2.f * acc[ii][2];
            v.w = w2 + csq[k0 + 3] - 2.f * acc[ii][3];
            *(float4*)(att + (i0 + ii) * LDP + k0) = v;
        }
        __syncthreads();

        // softmax(-sqrt(d2)) per row; 4 threads/row, 16 cols each
        {
            const int row = tid >> 2, q = tid & 3;
            float e[16];
            float mn = 3.4e38f;
#pragma unroll
            for (int j = 0; j < 16; j++) {
                float d2v = att[row * LDP + q * 16 + j];
                float dv = sqrtf(fmaxf(d2v, 0.f));
                e[j] = dv;
                mn = fminf(mn, dv);
            }
            mn = fminf(mn, __shfl_xor_sync(0xffffffffu, mn, 1));
            mn = fminf(mn, __shfl_xor_sync(0xffffffffu, mn, 2));
            float s = 0.f;
#pragma unroll
            for (int j = 0; j < 16; j++) {
                float ex = __expf(mn - e[j]);   // exp((min_dist - dist)/T), T=1
                e[j] = ex;
                s += ex;
            }
            s += __shfl_xor_sync(0xffffffffu, s, 1);
            s += __shfl_xor_sync(0xffffffffu, s, 2);
            float inv = 1.f / s;
            float* ga = attn_out + (size_t)(row0 + row) * KC + q * 16;
#pragma unroll
            for (int j4 = 0; j4 < 4; j4++) {
                float4 v;
                v.x = e[j4 * 4 + 0] * inv; v.y = e[j4 * 4 + 1] * inv;
                v.z = e[j4 * 4 + 2] * inv; v.w = e[j4 * 4 + 3] * inv;
                *(float4*)(att + row * LDP + q * 16 + j4 * 4) = v;
                *(float4*)(ga + j4 * 4) = v;
            }
        }
        __syncthreads();

        // GEMM2: c2[kk][dd] += sum_r attn[r][k0+kk] * W[r][i0+dd]  (i0 plays d0)
#pragma unroll 8
        for (int r = 0; r < TILE; r++) {
            float4 av = *(float4*)(att + r * LDP + k0);
            float4 bv = *(float4*)(wrow + r * 64 + i0);
            float a[4] = {av.x, av.y, av.z, av.w};
            float b[4] = {bv.x, bv.y, bv.z, bv.w};
#pragma unroll
            for (int kk = 0; kk < 4; kk++)
#pragma unroll
                for (int dd = 0; dd < 4; dd++)
                    c2[kk][dd] += a[kk] * b[dd];
            if (ty == 0) {   // one d-stripe accumulates colsum
                csum[0] += a[0]; csum[1] += a[1]; csum[2] += a[2]; csum[3] += a[3];
            }
        }
    }

    // write per-block partials (deterministic two-stage reduction, no atomics)
    float* P = g_part[blockIdx.x];
#pragma unroll
    for (int kk = 0; kk < 4; kk++) {
        float4 v = {c2[kk][0], c2[kk][1], c2[kk][2], c2[kk][3]};
        *(float4*)(P + (k0 + kk) * LDP + i0) = v;
    }
    if (ty == 0) {
#pragma unroll
        for (int kk = 0; kk < 4; kk++) P[(k0 + kk) * LDP + 64] = csum[kk];
    }
}

// ---------------- stage-2 reduction of partials ----------------
__global__ void reduce_kernel() {
    if (g_done) return;
    int idx = blockIdx.x * blockDim.x + threadIdx.x;
    if (idx >= KC * 65) return;
    int k = idx / 65, d = idx % 65;
    float s = 0.f;
    for (int b = 0; b < NBLK; b += 4) {
        s += g_part[b + 0][k * LDP + d] + g_part[b + 1][k * LDP + d]
           + g_part[b + 2][k * LDP + d] + g_part[b + 3][k * LDP + d];
    }
    g_S[k * LDP + d] = s;
}

// ---------------- cluster update + convergence (single block) ----------------
__global__ void update_kernel() {
    if (g_done) return;
    __shared__ float red[8];
    __shared__ int s_conv;
    int tid = threadIdx.x;
    float newv[16];
    float dsum = 0.f;
#pragma unroll
    for (int j = 0; j < 16; j++) {
        int idx = j * 256 + tid;
        int k = idx >> 6;
        float nv = g_S[k * LDP + (idx & 63)] / g_S[k * LDP + 64];
        newv[j] = nv;
        float diff = nv - g_clusters[idx];
        dsum += diff * diff;
    }
#pragma unroll
    for (int o = 16; o > 0; o >>= 1) dsum += __shfl_xor_sync(0xffffffffu, dsum, o);
    if ((tid & 31) == 0) red[tid >> 5] = dsum;
    __syncthreads();
    if (tid == 0) {
        float t = 0.f;
        for (int w = 0; w < 8; w++) t += red[w];
        s_conv = (sqrtf(t) <= 1e-4f) ? 1 : 0;   // Frobenius norm <= EPSILON
        if (s_conv) g_done = 1;                 // freeze: clusters NOT updated
    }
    __syncthreads();
    if (!s_conv) {
#pragma unroll
        for (int j = 0; j < 16; j++) g_clusters[j * 256 + tid] = newv[j];
    }
}

// ---------------- final: compressed = attn @ clusters; emit clusters ----------------
__global__ __launch_bounds__(TPB) void final_kernel(const float* __restrict__ attn,
                                                    float* __restrict__ comp,
                                                    float* __restrict__ clus_out) {
    __shared__ float cs[KC * DIM];   // clusters row-major [k][d]
    __shared__ float aT[KC * LDP];   // attn tile transposed [k][row]
    int tid = threadIdx.x;
    for (int i = tid; i < KC * DIM; i += TPB) {
        float v = g_clusters[i];
        cs[i] = v;
        if (blockIdx.x == 0) clus_out[i] = v;
    }
    size_t row0 = (size_t)blockIdx.x * TILE;
    for (int i = tid * 4; i < TILE * KC; i += TPB * 4) {
        float4 v = *(const float4*)(attn + row0 * KC + i);
        int r = i >> 6, k = i & 63;
        aT[(k + 0) * LDP + r] = v.x;
        aT[(k + 1) * LDP + r] = v.y;
        aT[(k + 2) * LDP + r] = v.z;
        aT[(k + 3) * LDP + r] = v.w;
    }
    __syncthreads();
    int tx = tid & 15, ty = tid >> 4;
    int i0 = ty * 4, d0 = tx * 4;
    float acc[4][4];
#pragma unroll
    for (int a = 0; a < 4; a++)
#pragma unroll
        for (int b = 0; b < 4; b++) acc[a][b] = 0.f;
#pragma unroll 8
    for (int k = 0; k < KC; k++) {
        float4 av = *(float4*)(aT + k * LDP + i0);
        float4 bv = *(float4*)(cs + k * 64 + d0);
        float a[4] = {av.x, av.y, av.z, av.w};
        float b[4] = {bv.x, bv.y, bv.z, bv.w};
#pragma unroll
        for (int ii = 0; ii < 4; ii++)
#pragma unroll
            for (int dd = 0; dd < 4; dd++)
                acc[ii][dd] += a[ii] * b[dd];
    }
#pragma unroll
    for (int ii = 0; ii < 4; ii++) {
        float4 v = {acc[ii][0], acc[ii][1], acc[ii][2], acc[ii][3]};
        *(float4*)(comp + (row0 + i0 + ii) * DIM + d0) = v;
    }
}

// ---------------- launch ----------------
extern "C" void kernel_launch(void* const* d_in, const int* in_sizes, int n_in,
                              void* d_out, int out_size) {
    const float* W  = (const float*)d_in[0];
    const float* C0 = (const float*)d_in[1];
    float* out  = (float*)d_out;
    float* comp = out;                                    // [N, D]
    float* clus = out + (size_t)NROWS * DIM;              // [K, D]
    float* attn = clus + (size_t)KC * DIM;                // [N, K]

    size_t smem = (size_t)(3 * 64 * LDP + 64 * 64 + 128) * sizeof(float);  // 69120 B
    cudaFuncSetAttribute(iter_kernel, cudaFuncAttributeMaxDynamicSharedMemorySize, (int)smem);

    init_kernel<<<NROWS / TPB, TPB>>>(W, C0);
    for (int it = 0; it < ITERS; it++) {
        iter_kernel<<<NBLK, TPB, smem>>>(W, attn);
        reduce_kernel<<<(KC * 65 + TPB - 1) / TPB, TPB>>>();
        update_kernel<<<1, TPB>>>();
    }
    final_kernel<<<NTILES, TPB>>>(attn, comp, clus);
}

// round 3
// speedup vs baseline: 1.0127x; 1.0108x over previous
#include <cuda_runtime.h>
#include <math.h>

#define NROWS 131072
#define DIM 64
#define KC 64
#define TILE 64
#define NTILES 2048          // NROWS / TILE
#define NBLK 512
#define TPB 256
#define ITERS 10
#define LDP 68               // padded stride (floats) for conflict-free smem

// ---------------- device globals (no cudaMalloc allowed) ----------------
__device__ float g_clusters[KC * DIM];
__device__ float g_S[KC * LDP];              // reduced sums: [k*LDP+d], d==64 -> colsum
__device__ float g_part[NBLK][KC * LDP];     // per-block partials
__device__ float g_wsq[NROWS];
__device__ int   g_done;

// ---------------- init: done flag, cluster copy, ||w||^2 ----------------
__global__ void init_kernel(const float* __restrict__ W, const float* __restrict__ C0) {
    int gid = blockIdx.x * blockDim.x + threadIdx.x;   // grid == NROWS threads exactly
    if (gid == 0) g_done = 0;
    if (gid < KC * DIM) g_clusters[gid] = C0[gid];
    const float4* p = (const float4*)(W + (size_t)gid * DIM);
    float s = 0.f;
#pragma unroll
    for (int j = 0; j < 16; j++) {
        float4 v = p[j];
        s += v.x * v.x + v.y * v.y + v.z * v.z + v.w * v.w;
    }
    g_wsq[gid] = s;
}

// ---------------- fused iteration kernel ----------------
// Per 64-row tile: d2 = ||w||^2 + ||c||^2 - 2 W C^T  -> softmax(-sqrt(d2)) ->
// write attn to gmem, accumulate attn^T W (+colsum) into per-block registers.
__global__ __launch_bounds__(TPB, 3) void iter_kernel(const float* __restrict__ W,
                                                      float* __restrict__ attn_out) {
    if (g_done) return;
    extern __shared__ float sm[];
    float* csT  = sm;                      // [64][LDP]  clusters transposed: csT[d*LDP+k]
    float* wsT  = sm + 64 * LDP;           // [64][LDP]  W tile transposed:  wsT[d*LDP+r]
    float* wrow = sm + 2 * 64 * LDP;       // [64][64]   W tile row-major
    float* att  = sm + 2 * 64 * LDP + 64 * 64;  // [64][LDP] d2 then attn
    float* csq  = att + 64 * LDP;          // [64]
    float* wsq  = csq + 64;                // [64]

    const int tid = threadIdx.x;
    const int tx = tid & 15, ty = tid >> 4;
    const int i0 = ty * 4, k0 = tx * 4;

    // load + transpose clusters (persistent for this kernel)
    for (int i = tid; i < KC * DIM; i += TPB) {
        float v = g_clusters[i];
        csT[(i & 63) * LDP + (i >> 6)] = v;
    }
    __syncthreads();
    if (tid < KC) {
        float s = 0.f;
#pragma unroll
        for (int d = 0; d < DIM; d++) { float v = csT[d * LDP + tid]; s += v * v; }
        csq[tid] = s;
    }

    float c2[4][4];
#pragma unroll
    for (int a = 0; a < 4; a++)
#pragma unroll
        for (int b = 0; b < 4; b++) c2[a][b] = 0.f;
    float csum[4] = {0.f, 0.f, 0.f, 0.f};

    for (int tile = blockIdx.x; tile < NTILES; tile += NBLK) {
        const int row0 = tile * TILE;
        __syncthreads();   // prev GEMM2 done (and csq ready on first pass)

        // load W tile into both layouts
        for (int i = tid * 4; i < TILE * DIM; i += TPB * 4) {
            float4 v = *(const float4*)(W + (size_t)row0 * DIM + i);
            int r = i >> 6, d = i & 63;
            *(float4*)(wrow + r * 64 + d) = v;
            wsT[(d + 0) * LDP + r] = v.x;
            wsT[(d + 1) * LDP + r] = v.y;
            wsT[(d + 2) * LDP + r] = v.z;
            wsT[(d + 3) * LDP + r] = v.w;
        }
        if (tid < TILE) wsq[tid] = g_wsq[row0 + tid];
        __syncthreads();

        // GEMM1: acc[ii][kk] = dot(w_{i0+ii}, c_{k0+kk})
        float acc[4][4];
#pragma unroll
        for (int a = 0; a < 4; a++)
#pragma unroll
            for (int b = 0; b < 4; b++) acc[a][b] = 0.f;
#pragma unroll 8
        for (int d = 0; d < DIM; d++) {
            float4 av = *(float4*)(wsT + d * LDP + i0);
            float4 bv = *(float4*)(csT + d * LDP + k0);
            float a[4] = {av.x, av.y, av.z, av.w};
            float b[4] = {bv.x, bv.y, bv.z, bv.w};
#pragma unroll
            for (int ii = 0; ii < 4; ii++)
#pragma unroll
                for (int kk = 0; kk < 4; kk++)
                    acc[ii][kk] += a[ii] * b[kk];
        }
        // d2 -> smem
#pragma unroll
        for (int ii = 0; ii < 4; ii++) {
            float w2 = wsq[i0 + ii];
            float4 v;
            v.x = w2 + csq[k0 + 0] - 2.f * acc[ii][0];
            v.y = w2 + csq[k0 + 1] - 2.f * acc[ii][1];
            v.z = w2 + csq[k0 + 2] - 2.f * acc[ii][2];
            v.w = w2 + csq[k0 + 3] - 2.f * acc[ii][3];
            *(float4*)(att + (i0 + ii) * LDP + k0) = v;
        }
        __syncthreads();

        // softmax(-sqrt(d2)) per row; 4 threads/row, 16 cols each
        {
            const int row = tid >> 2, q = tid & 3;
            float e[16];
            float mn = 3.4e38f;
#pragma unroll
            for (int j = 0; j < 16; j++) {
                float d2v = att[row * LDP + q * 16 + j];
                float dv = sqrtf(fmaxf(d2v, 0.f));
                e[j] = dv;
                mn = fminf(mn, dv);
            }
            mn = fminf(mn, __shfl_xor_sync(0xffffffffu, mn, 1));
            mn = fminf(mn, __shfl_xor_sync(0xffffffffu, mn, 2));
            float s = 0.f;
#pragma unroll
            for (int j = 0; j < 16; j++) {
                float ex = __expf(mn - e[j]);   // exp((min_dist - dist)/T), T=1
                e[j] = ex;
                s += ex;
            }
            s += __shfl_xor_sync(0xffffffffu, s, 1);
            s += __shfl_xor_sync(0xffffffffu, s, 2);
            float inv = 1.f / s;
            float* ga = attn_out + (size_t)(row0 + row) * KC + q * 16;
#pragma unroll
            for (int j4 = 0; j4 < 4; j4++) {
                float4 v;
                v.x = e[j4 * 4 + 0] * inv; v.y = e[j4 * 4 + 1] * inv;
                v.z = e[j4 * 4 + 2] * inv; v.w = e[j4 * 4 + 3] * inv;
                *(float4*)(att + row * LDP + q * 16 + j4 * 4) = v;
                *(float4*)(ga + j4 * 4) = v;
            }
        }
        __syncthreads();

        // GEMM2: c2[kk][dd] += sum_r attn[r][k0+kk] * W[r][i0+dd]  (i0 plays d0)
#pragma unroll 8
        for (int r = 0; r < TILE; r++) {
            float4 av = *(float4*)(att + r * LDP + k0);
            float4 bv = *(float4*)(wrow + r * 64 + i0);
            float a[4] = {av.x, av.y, av.z, av.w};
            float b[4] = {bv.x, bv.y, bv.z, bv.w};
#pragma unroll
            for (int kk = 0; kk < 4; kk++)
#pragma unroll
                for (int dd = 0; dd < 4; dd++)
                    c2[kk][dd] += a[kk] * b[dd];
            if (ty == 0) {   // one d-stripe accumulates colsum
                csum[0] += a[0]; csum[1] += a[1]; csum[2] += a[2]; csum[3] += a[3];
            }
        }
    }

    // write per-block partials (deterministic two-stage reduction, no atomics)
    float* P = g_part[blockIdx.x];
#pragma unroll
    for (int kk = 0; kk < 4; kk++) {
        float4 v = {c2[kk][0], c2[kk][1], c2[kk][2], c2[kk][3]};
        *(float4*)(P + (k0 + kk) * LDP + i0) = v;
    }
    if (ty == 0) {
#pragma unroll
        for (int kk = 0; kk < 4; kk++) P[(k0 + kk) * LDP + 64] = csum[kk];
    }
}

// ---------------- stage-2 reduction of partials ----------------
__global__ void reduce_kernel() {
    if (g_done) return;
    int idx = blockIdx.x * blockDim.x + threadIdx.x;
    if (idx >= KC * 65) return;
    int k = idx / 65, d = idx % 65;
    float s = 0.f;
    for (int b = 0; b < NBLK; b += 4) {
        s += g_part[b + 0][k * LDP + d] + g_part[b + 1][k * LDP + d]
           + g_part[b + 2][k * LDP + d] + g_part[b + 3][k * LDP + d];
    }
    g_S[k * LDP + d] = s;
}

// ---------------- cluster update + convergence (single block) ----------------
__global__ void update_kernel() {
    if (g_done) return;
    __shared__ float red[8];
    __shared__ int s_conv;
    int tid = threadIdx.x;
    float newv[16];
    float dsum = 0.f;
#pragma unroll
    for (int j = 0; j < 16; j++) {
        int idx = j * 256 + tid;
        int k = idx >> 6;
        float nv = g_S[k * LDP + (idx & 63)] / g_S[k * LDP + 64];
        newv[j] = nv;
        float diff = nv - g_clusters[idx];
        dsum += diff * diff;
    }
#pragma unroll
    for (int o = 16; o > 0; o >>= 1) dsum += __shfl_xor_sync(0xffffffffu, dsum, o);
    if ((tid & 31) == 0) red[tid >> 5] = dsum;
    __syncthreads();
    if (tid == 0) {
        float t = 0.f;
        for (int w = 0; w < 8; w++) t += red[w];
        s_conv = (sqrtf(t) <= 1e-4f) ? 1 : 0;   // Frobenius norm <= EPSILON
        if (s_conv) g_done = 1;                 // freeze: clusters NOT updated
    }
    __syncthreads();
    if (!s_conv) {
#pragma unroll
        for (int j = 0; j < 16; j++) g_clusters[j * 256 + tid] = newv[j];
    }
}

// ---------------- final: compressed = attn @ clusters; emit clusters ----------------
__global__ __launch_bounds__(TPB) void final_kernel(const float* __restrict__ attn,
                                                    float* __restrict__ comp,
                                                    float* __restrict__ clus_out) {
    __shared__ float cs[KC * DIM];   // clusters row-major [k][d]
    __shared__ float aT[KC * LDP];   // attn tile transposed [k][row]
    int tid = threadIdx.x;
    for (int i = tid; i < KC * DIM; i += TPB) {
        float v = g_clusters[i];
        cs[i] = v;
        if (blockIdx.x == 0) clus_out[i] = v;
    }
    size_t row0 = (size_t)blockIdx.x * TILE;
    for (int i = tid * 4; i < TILE * KC; i += TPB * 4) {
        float4 v = *(const float4*)(attn + row0 * KC + i);
        int r = i >> 6, k = i & 63;
        aT[(k + 0) * LDP + r] = v.x;
        aT[(k + 1) * LDP + r] = v.y;
        aT[(k + 2) * LDP + r] = v.z;
        aT[(k + 3) * LDP + r] = v.w;
    }
    __syncthreads();
    int tx = tid & 15, ty = tid >> 4;
    int i0 = ty * 4, d0 = tx * 4;
    float acc[4][4];
#pragma unroll
    for (int a = 0; a < 4; a++)
#pragma unroll
        for (int b = 0; b < 4; b++) acc[a][b] = 0.f;
#pragma unroll 8
    for (int k = 0; k < KC; k++) {
        float4 av = *(float4*)(aT + k * LDP + i0);
        float4 bv = *(float4*)(cs + k * 64 + d0);
        float a[4] = {av.x, av.y, av.z, av.w};
        float b[4] = {bv.x, bv.y, bv.z, bv.w};
#pragma unroll
        for (int ii = 0; ii < 4; ii++)
#pragma unroll
            for (int dd = 0; dd < 4; dd++)
                acc[ii][dd] += a[ii] * b[dd];
    }
#pragma unroll
    for (int ii = 0; ii < 4; ii++) {
        float4 v = {acc[ii][0], acc[ii][1], acc[ii][2], acc[ii][3]};
        *(float4*)(comp + (row0 + i0 + ii) * DIM + d0) = v;
    }
}

// ---------------- launch ----------------
extern "C" void kernel_launch(void* const* d_in, const int* in_sizes, int n_in,
                              void* d_out, int out_size) {
    const float* W  = (const float*)d_in[0];
    const float* C0 = (const float*)d_in[1];
    float* out  = (float*)d_out;
    float* comp = out;                                    // [N, D]
    float* clus = out + (size_t)NROWS * DIM;              // [K, D]
    float* attn = clus + (size_t)KC * DIM;                // [N, K]

    size_t smem = (size_t)(3 * 64 * LDP + 64 * 64 + 128) * sizeof(float);  // 69120 B
    cudaFuncSetAttribute(iter_kernel, cudaFuncAttributeMaxDynamicSharedMemorySize, (int)smem);

    init_kernel<<<NROWS / TPB, TPB>>>(W, C0);
    for (int it = 0; it < ITERS; it++) {
        iter_kernel<<<NBLK, TPB, smem>>>(W, attn);
        reduce_kernel<<<(KC * 65 + TPB - 1) / TPB, TPB>>>();
        update_kernel<<<1, TPB>>>();
    }
    final_kernel<<<NTILES, TPB>>>(attn, comp, clus);
}

// round 4
// speedup vs baseline: 1.7578x; 1.7358x over previous
#include <cuda_runtime.h>
#include <math.h>
#include <stdint.h>

#define NROWS 131072
#define DIM 64
#define KC 64
#define ITERS 10
#define TPB 256
#define MT 128                    // rows per tile in mma iteration kernel
#define NT (NROWS / MT)           // 1024 tiles
#define GRID_MMA 148
#define NPART (GRID_MMA * 2)      // 296 partial slots (block x row-half)
#define PSTR (64 * 68)            // 4352 floats per partial slot

// ---------------- device globals (no cudaMalloc allowed) ----------------
__device__ float g_clusters[KC * DIM];
__device__ float g_prev[KC * DIM];          // clusters used by last active iteration
__device__ float g_wtf[NROWS * DIM];        // tf32-rounded copy of W
__device__ float g_S[KC * 68];              // reduced sums: [k*68+d], d==64 -> colsum
__device__ float g_part[(size_t)NPART * PSTR];
__device__ float g_wsq[NROWS];
__device__ int   g_done;

// ---------------- helpers ----------------
__device__ __forceinline__ uint32_t f2t(float x) {
    uint32_t u;
    asm("cvt.rna.tf32.f32 %0, %1;" : "=r"(u) : "f"(x));
    return u;
}
__device__ __forceinline__ void mma8(float c[4], uint32_t a0, uint32_t a1, uint32_t a2,
                                     uint32_t a3, uint32_t b0, uint32_t b1) {
    asm volatile(
        "mma.sync.aligned.m16n8k8.row.col.f32.tf32.tf32.f32 "
        "{%0,%1,%2,%3},{%4,%5,%6,%7},{%8,%9},{%0,%1,%2,%3};"
        : "+f"(c[0]), "+f"(c[1]), "+f"(c[2]), "+f"(c[3])
        : "r"(a0), "r"(a1), "r"(a2), "r"(a3), "r"(b0), "r"(b1));
}
#define BITS(x) (__float_as_uint(x))

// ---------------- init: done flag, cluster copy, ||w||^2, tf32 W copy ----------------
__global__ void init_kernel(const float* __restrict__ W, const float* __restrict__ C0) {
    int gid = blockIdx.x * blockDim.x + threadIdx.x;   // NROWS threads
    if (gid == 0) g_done = 0;
    if (gid < KC * DIM) g_clusters[gid] = C0[gid];
    // wsq from ORIGINAL weights
    const float4* p = (const float4*)(W + (size_t)gid * DIM);
    float s = 0.f;
#pragma unroll
    for (int j = 0; j < 16; j++) {
        float4 v = p[j];
        s += v.x * v.x + v.y * v.y + v.z * v.z + v.w * v.w;
    }
    g_wsq[gid] = s;
    // coalesced tf32-rounded copy of W
    const float4* w4 = (const float4*)W;
    float4* o4 = (float4*)g_wtf;
#pragma unroll
    for (int j = 0; j < 16; j++) {
        size_t idx = (size_t)gid + (size_t)j * NROWS;
        float4 v = w4[idx];
        v.x = __uint_as_float(f2t(v.x));
        v.y = __uint_as_float(f2t(v.y));
        v.z = __uint_as_float(f2t(v.z));
        v.w = __uint_as_float(f2t(v.w));
        o4[idx] = v;
    }
}

// ---------------- fused iteration kernel (tensor-core tf32) ----------------
// Per 128-row tile: d2 via mma (W*C^T) -> softmax in registers -> attn (tf32) to smem
// -> attn^T * W via mma into per-warp accumulators; partials written at kernel end.
__global__ __launch_bounds__(TPB, 1) void iter_mma() {
    if (g_done) return;
    extern __shared__ float sm[];
    float* cl    = sm;            // [64][68] clusters (tf32-rounded), row-major [k][d]
    float* csq   = sm + 4352;     // [64] exact ||c||^2
    float* wrow  = sm + 4416;     // [128][68] W tile (GEMM1 A: gid-major rows)
    float* wrow2 = sm + 13120;    // [128][72] W tile + ones col (GEMM2 B: tig-major rows)
    float* att   = sm + 22336;    // [128][72] attn tile (GEMM2 A)
    float* wsqs  = sm + 31552;    // [128]

    const int tid = threadIdx.x;
    const int lane = tid & 31, wid = tid >> 5;
    const int gid = lane >> 2, tig = lane & 3;
    const int m1 = wid * 16;            // GEMM1 row offset
    const int m2 = (wid & 3) * 16;      // GEMM2 kc offset
    const int rh = (wid >> 2) * 64;     // GEMM2 row-half offset

    for (int i = tid; i < KC * DIM; i += TPB)
        cl[(i >> 6) * 68 + (i & 63)] = __uint_as_float(f2t(g_clusters[i]));
    if (tid < KC) {
        float s = 0.f;
#pragma unroll
        for (int d = 0; d < DIM; d++) { float v = g_clusters[tid * DIM + d]; s += v * v; }
        csq[tid] = s;
    }
    __syncthreads();
    float csqL[8], csqR[8];
#pragma unroll
    for (int j = 0; j < 8; j++) { csqL[j] = csq[8 * j + 2 * tig]; csqR[j] = csq[8 * j + 2 * tig + 1]; }

    float c2[9][4];
#pragma unroll
    for (int j = 0; j < 9; j++) { c2[j][0] = c2[j][1] = c2[j][2] = c2[j][3] = 0.f; }

    for (int tile = blockIdx.x; tile < NT; tile += GRID_MMA) {
        const size_t row0 = (size_t)tile * MT;
        __syncthreads();
        for (int i = tid * 4; i < MT * DIM; i += TPB * 4) {
            float4 v = *(const float4*)(g_wtf + row0 * DIM + i);
            int r = i >> 6, d = i & 63;
            *(float4*)(wrow + r * 68 + d) = v;
            *(float4*)(wrow2 + r * 72 + d) = v;
        }
        if (tid < MT) { wrow2[tid * 72 + 64] = 1.0f; wsqs[tid] = g_wsq[row0 + tid]; }
        __syncthreads();

        // ---- GEMM1: C1[row][kc] = W * C^T ----
        float c1[8][4];
#pragma unroll
        for (int j = 0; j < 8; j++) { c1[j][0] = c1[j][1] = c1[j][2] = c1[j][3] = 0.f; }
        const float* Ab = wrow + (m1 + gid) * 68 + tig;
#pragma unroll 4
        for (int s = 0; s < 8; s++) {
            const int k0 = 8 * s;
            uint32_t a0 = BITS(Ab[k0]);
            uint32_t a1 = BITS(Ab[8 * 68 + k0]);
            uint32_t a2 = BITS(Ab[k0 + 4]);
            uint32_t a3 = BITS(Ab[8 * 68 + k0 + 4]);
            const float* Bb = cl + gid * 68 + k0 + tig;
#pragma unroll
            for (int j = 0; j < 8; j++) {
                uint32_t b0 = BITS(Bb[j * 8 * 68]);
                uint32_t b1 = BITS(Bb[j * 8 * 68 + 4]);
                mma8(c1[j], a0, a1, a2, a3, b0, b1);
            }
        }

        // ---- softmax in registers (rows m1+gid and m1+gid+8; quad = 4 lanes/row) ----
        float wsA = wsqs[m1 + gid], wsB = wsqs[m1 + gid + 8];
        float eA[16], eB[16], mnA = 3.4e38f, mnB = 3.4e38f;
#pragma unroll
        for (int j = 0; j < 8; j++) {
            float dA0 = sqrtf(fmaxf(wsA + csqL[j] - 2.f * c1[j][0], 0.f));
            float dA1 = sqrtf(fmaxf(wsA + csqR[j] - 2.f * c1[j][1], 0.f));
            float dB0 = sqrtf(fmaxf(wsB + csqL[j] - 2.f * c1[j][2], 0.f));
            float dB1 = sqrtf(fmaxf(wsB + csqR[j] - 2.f * c1[j][3], 0.f));
            eA[2 * j] = dA0; eA[2 * j + 1] = dA1;
            eB[2 * j] = dB0; eB[2 * j + 1] = dB1;
            mnA = fminf(mnA, fminf(dA0, dA1));
            mnB = fminf(mnB, fminf(dB0, dB1));
        }
        mnA = fminf(mnA, __shfl_xor_sync(0xffffffffu, mnA, 1));
        mnA = fminf(mnA, __shfl_xor_sync(0xffffffffu, mnA, 2));
        mnB = fminf(mnB, __shfl_xor_sync(0xffffffffu, mnB, 1));
        mnB = fminf(mnB, __shfl_xor_sync(0xffffffffu, mnB, 2));
        float sA = 0.f, sB = 0.f;
#pragma unroll
        for (int j = 0; j < 16; j++) {
            eA[j] = __expf(mnA - eA[j]); sA += eA[j];
            eB[j] = __expf(mnB - eB[j]); sB += eB[j];
        }
        sA += __shfl_xor_sync(0xffffffffu, sA, 1);
        sA += __shfl_xor_sync(0xffffffffu, sA, 2);
        sB += __shfl_xor_sync(0xffffffffu, sB, 1);
        sB += __shfl_xor_sync(0xffffffffu, sB, 2);
        float iA = 1.f / sA, iB = 1.f / sB;
        float* wA = att + (m1 + gid) * 72 + 2 * tig;
        float* wB = att + (m1 + gid + 8) * 72 + 2 * tig;
#pragma unroll
        for (int j = 0; j < 8; j++) {
            float2 vA = make_float2(__uint_as_float(f2t(eA[2 * j] * iA)),
                                    __uint_as_float(f2t(eA[2 * j + 1] * iA)));
            float2 vB = make_float2(__uint_as_float(f2t(eB[2 * j] * iB)),
                                    __uint_as_float(f2t(eB[2 * j + 1] * iB)));
            *(float2*)(wA + 8 * j) = vA;
            *(float2*)(wB + 8 * j) = vB;
        }
        __syncthreads();

        // ---- GEMM2: C2[kc][d] += attn^T * W  (9th n-frag vs ones col = colsum) ----
        const float* A2 = att + (rh + tig) * 72 + m2 + gid;
        const float* B2 = wrow2 + (rh + tig) * 72 + gid;
#pragma unroll 4
        for (int s = 0; s < 8; s++) {
            const int o = s * 8 * 72;
            uint32_t a0 = BITS(A2[o]);
            uint32_t a1 = BITS(A2[o + 8]);
            uint32_t a2 = BITS(A2[o + 4 * 72]);
            uint32_t a3 = BITS(A2[o + 4 * 72 + 8]);
#pragma unroll
            for (int j = 0; j < 9; j++) {
                uint32_t b0 = BITS(B2[o + 8 * j]);
                uint32_t b1 = BITS(B2[o + 4 * 72 + 8 * j]);
                mma8(c2[j], a0, a1, a2, a3, b0, b1);
            }
        }
    }

    // per-(block, row-half) partials: deterministic two-stage reduction, no atomics
    float* P = g_part + (size_t)(blockIdx.x * 2 + (wid >> 2)) * PSTR;
#pragma unroll
    for (int j = 0; j < 8; j++) {
        *(float2*)(P + (m2 + gid) * 68 + 8 * j + 2 * tig) = make_float2(c2[j][0], c2[j][1]);
        *(float2*)(P + (m2 + gid + 8) * 68 + 8 * j + 2 * tig) = make_float2(c2[j][2], c2[j][3]);
    }
    if (tig == 0) {
        P[(m2 + gid) * 68 + 64] = c2[8][0];       // colsum (B col 64 == 1.0)
        P[(m2 + gid + 8) * 68 + 64] = c2[8][2];
    }
}

// ---------------- stage-2 reduction of partials ----------------
__global__ void reduce_kernel() {
    if (g_done) return;
    int idx = blockIdx.x * blockDim.x + threadIdx.x;
    if (idx >= KC * 65) return;
    int k = idx / 65, d = idx - k * 65;
    const float* p = g_part + k * 68 + d;
    float s0 = 0.f, s1 = 0.f, s2 = 0.f, s3 = 0.f;
#pragma unroll 4
    for (int b = 0; b < NPART; b += 4) {
        s0 += p[(size_t)b * PSTR];
        s1 += p[(size_t)(b + 1) * PSTR];
        s2 += p[(size_t)(b + 2) * PSTR];
        s3 += p[(size_t)(b + 3) * PSTR];
    }
    g_S[k * 68 + d] = (s0 + s1) + (s2 + s3);
}

// ---------------- cluster update + convergence (single block) ----------------
__global__ void update_kernel() {
    if (g_done) return;
    __shared__ float red[8];
    __shared__ int s_conv;
    int tid = threadIdx.x;
    float newv[16];
    float dsum = 0.f;
#pragma unroll
    for (int j = 0; j < 16; j++) {
        int idx = j * 256 + tid;
        int k = idx >> 6;
        float ov = g_clusters[idx];
        g_prev[idx] = ov;                              // clusters used by this iteration
        float nv = g_S[k * 68 + (idx & 63)] / g_S[k * 68 + 64];
        newv[j] = nv;
        float diff = nv - ov;
        dsum += diff * diff;
    }
#pragma unroll
    for (int o = 16; o > 0; o >>= 1) dsum += __shfl_xor_sync(0xffffffffu, dsum, o);
    if ((tid & 31) == 0) red[tid >> 5] = dsum;
    __syncthreads();
    if (tid == 0) {
        float t = 0.f;
        for (int w = 0; w < 8; w++) t += red[w];
        s_conv = (sqrtf(t) <= 1e-4f) ? 1 : 0;
        if (s_conv) g_done = 1;                        // freeze: clusters NOT updated
    }
    __syncthreads();
    if (!s_conv) {
#pragma unroll
        for (int j = 0; j < 16; j++) g_clusters[j * 256 + tid] = newv[j];
    }
}

// ---------------- final attn pass: full fp32 vs g_prev (output-critical) ----------------
__global__ __launch_bounds__(TPB) void attn_final_kernel(const float* __restrict__ W,
                                                         float* __restrict__ attn_out) {
    extern __shared__ float sm[];
    float* csT = sm;                 // [64][68] prev clusters transposed [d][k]
    float* wsT = sm + 64 * 68;       // [64][68] W tile transposed [d][r]
    float* att = sm + 2 * 64 * 68;   // [64][68] d2
    float* csq = sm + 3 * 64 * 68;
    float* wsq = csq + 64;
    const int tid = threadIdx.x;
    const int tx = tid & 15, ty = tid >> 4;
    const int i0 = ty * 4, k0 = tx * 4;

    for (int i = tid; i < KC * DIM; i += TPB) {
        float v = g_prev[i];
        csT[(i & 63) * 68 + (i >> 6)] = v;
    }
    __syncthreads();
    if (tid < KC) {
        float s = 0.f;
#pragma unroll
        for (int d = 0; d < DIM; d++) { float v = csT[d * 68 + tid]; s += v * v; }
        csq[tid] = s;
    }
    const int row0 = blockIdx.x * 64;
    for (int i = tid * 4; i < 64 * DIM; i += TPB * 4) {
        float4 v = *(const float4*)(W + (size_t)row0 * DIM + i);
        int r = i >> 6, d = i & 63;
        wsT[(d + 0) * 68 + r] = v.x;
        wsT[(d + 1) * 68 + r] = v.y;
        wsT[(d + 2) * 68 + r] = v.z;
        wsT[(d + 3) * 68 + r] = v.w;
    }
    if (tid < 64) wsq[tid] = g_wsq[row0 + tid];
    __syncthreads();

    float acc[4][4];
#pragma unroll
    for (int a = 0; a < 4; a++)
#pragma unroll
        for (int b = 0; b < 4; b++) acc[a][b] = 0.f;
#pragma unroll 8
    for (int d = 0; d < DIM; d++) {
        float4 av = *(float4*)(wsT + d * 68 + i0);
        float4 bv = *(float4*)(csT + d * 68 + k0);
        float a[4] = {av.x, av.y, av.z, av.w};
        float b[4] = {bv.x, bv.y, bv.z, bv.w};
#pragma unroll
        for (int ii = 0; ii < 4; ii++)
#pragma unroll
            for (int kk = 0; kk < 4; kk++) acc[ii][kk] += a[ii] * b[kk];
    }
#pragma unroll
    for (int ii = 0; ii < 4; ii++) {
        float w2 = wsq[i0 + ii];
        float4 v;
        v.x = w2 + csq[k0 + 0] - 2.f * acc[ii][0];
        v.y = w2 + csq[k0 + 1] - 2.f * acc[ii][1];
        v.z = w2 + csq[k0 + 2] - 2.f * acc[ii][2];
        v.w = w2 + csq[k0 + 3] - 2.f * acc[ii][3];
        *(float4*)(att + (i0 + ii) * 68 + k0) = v;
    }
    __syncthreads();

    {
        const int row = tid >> 2, q = tid & 3;
        float e[16];
        float mn = 3.4e38f;
#pragma unroll
        for (int j = 0; j < 16; j++) {
            float d2v = att[row * 68 + q * 16 + j];
            float dv = sqrtf(fmaxf(d2v, 0.f));
            e[j] = dv;
            mn = fminf(mn, dv);
        }
        mn = fminf(mn, __shfl_xor_sync(0xffffffffu, mn, 1));
        mn = fminf(mn, __shfl_xor_sync(0xffffffffu, mn, 2));
        float s = 0.f;
#pragma unroll
        for (int j = 0; j < 16; j++) {
            float ex = __expf(mn - e[j]);
            e[j] = ex;
            s += ex;
        }
        s += __shfl_xor_sync(0xffffffffu, s, 1);
        s += __shfl_xor_sync(0xffffffffu, s, 2);
        float inv = 1.f / s;
        float* ga = attn_out + (size_t)(row0 + row) * KC + q * 16;
#pragma unroll
        for (int j4 = 0; j4 < 4; j4++) {
            float4 v;
            v.x = e[j4 * 4 + 0] * inv; v.y = e[j4 * 4 + 1] * inv;
            v.z = e[j4 * 4 + 2] * inv; v.w = e[j4 * 4 + 3] * inv;
            *(float4*)(ga + j4 * 4) = v;
        }
    }
}

// ---------------- final: compressed = attn @ clusters; emit clusters ----------------
__global__ __launch_bounds__(TPB) void final_kernel(const float* __restrict__ attn,
                                                    float* __restrict__ comp,
                                                    float* __restrict__ clus_out) {
    __shared__ float cs[KC * DIM];   // clusters row-major
    __shared__ float aT[KC * 68];    // attn tile transposed [k][row]
    int tid = threadIdx.x;
    for (int i = tid; i < KC * DIM; i += TPB) {
        float v = g_clusters[i];
        cs[i] = v;
        if (blockIdx.x == 0) clus_out[i] = v;
    }
    size_t row0 = (size_t)blockIdx.x * 64;
    for (int i = tid * 4; i < 64 * KC; i += TPB * 4) {
        float4 v = *(const float4*)(attn + row0 * KC + i);
        int r = i >> 6, k = i & 63;
        aT[(k + 0) * 68 + r] = v.x;
        aT[(k + 1) * 68 + r] = v.y;
        aT[(k + 2) * 68 + r] = v.z;
        aT[(k + 3) * 68 + r] = v.w;
    }
    __syncthreads();
    int tx = tid & 15, ty = tid >> 4;
    int i0 = ty * 4, d0 = tx * 4;
    float acc[4][4];
#pragma unroll
    for (int a = 0; a < 4; a++)
#pragma unroll
        for (int b = 0; b < 4; b++) acc[a][b] = 0.f;
#pragma unroll 8
    for (int k = 0; k < KC; k++) {
        float4 av = *(float4*)(aT + k * 68 + i0);
        float4 bv = *(float4*)(cs + k * 64 + d0);
        float a[4] = {av.x, av.y, av.z, av.w};
        float b[4] = {bv.x, bv.y, bv.z, bv.w};
#pragma unroll
        for (int ii = 0; ii < 4; ii++)
#pragma unroll
            for (int dd = 0; dd < 4; dd++) acc[ii][dd] += a[ii] * b[dd];
    }
#pragma unroll
    for (int ii = 0; ii < 4; ii++) {
        float4 v = {acc[ii][0], acc[ii][1], acc[ii][2], acc[ii][3]};
        *(float4*)(comp + (row0 + i0 + ii) * DIM + d0) = v;
    }
}

// ---------------- launch ----------------
extern "C" void kernel_launch(void* const* d_in, const int* in_sizes, int n_in,
                              void* d_out, int out_size) {
    const float* W  = (const float*)d_in[0];
    const float* C0 = (const float*)d_in[1];
    float* out  = (float*)d_out;
    float* comp = out;                                    // [N, D]
    float* clus = out + (size_t)NROWS * DIM;              // [K, D]
    float* attn = clus + (size_t)KC * DIM;                // [N, K]

    const int smem_iter = 31680 * (int)sizeof(float);     // 126720 B
    const int smem_attn = (3 * 64 * 68 + 128) * (int)sizeof(float);
    cudaFuncSetAttribute(iter_mma, cudaFuncAttributeMaxDynamicSharedMemorySize, smem_iter);
    cudaFuncSetAttribute(attn_final_kernel, cudaFuncAttributeMaxDynamicSharedMemorySize, smem_attn);

    init_kernel<<<NROWS / TPB, TPB>>>(W, C0);
    for (int it = 0; it < ITERS; it++) {
        iter_mma<<<GRID_MMA, TPB, smem_iter>>>();
        reduce_kernel<<<(KC * 65 + 127) / 128, 128>>>();
        update_kernel<<<1, TPB>>>();
    }
    attn_final_kernel<<<NROWS / 64, TPB, smem_attn>>>(W, attn);
    final_kernel<<<NROWS / 64, TPB>>>(attn, comp, clus);
}

// round 5
// speedup vs baseline: 2.0481x; 1.1651x over previous
#include <cuda_runtime.h>
#include <math.h>
#include <stdint.h>

#define NROWS 131072
#define DIM 64
#define KC 64
#define ITERS 10
#define TPB 256
#define MT 128                    // rows per tile in mma iteration kernel
#define NT (NROWS / MT)           // 1024 tiles
#define MAXGRID 148
#define PSTR (64 * 68)            // 4352 floats per partial slot

// ---------------- device globals (no cudaMalloc allowed) ----------------
__device__ float g_clusters[KC * DIM];
__device__ float g_prev[KC * DIM];          // clusters used by last active iteration
__device__ float g_S_unused;                // (kept out: reduction now in-kernel)
__device__ float g_part[(size_t)(2 * MAXGRID) * PSTR];
__device__ float g_normk[KC];
__device__ float g_wsq[NROWS];
__device__ int   g_done;
__device__ int   g_commit;
__device__ volatile int g_sync[3];

// ---------------- helpers ----------------
__device__ __forceinline__ uint32_t f2t(float x) {
    uint32_t u;
    asm("cvt.rna.tf32.f32 %0, %1;" : "=r"(u) : "f"(x));
    return u;
}
__device__ __forceinline__ void mma8(float c[4], uint32_t a0, uint32_t a1, uint32_t a2,
                                     uint32_t a3, uint32_t b0, uint32_t b1) {
    asm volatile(
        "mma.sync.aligned.m16n8k8.row.col.f32.tf32.tf32.f32 "
        "{%0,%1,%2,%3},{%4,%5,%6,%7},{%8,%9},{%0,%1,%2,%3};"
        : "+f"(c[0]), "+f"(c[1]), "+f"(c[2]), "+f"(c[3])
        : "r"(a0), "r"(a1), "r"(a2), "r"(a3), "r"(b0), "r"(b1));
}
#define BITS(x) (__float_as_uint(x))

// deterministic grid-wide sync: monotonic counters, per-launch target
__device__ __forceinline__ void gsync(int j, int target) {
    __syncthreads();
    if (threadIdx.x == 0) {
        __threadfence();                       // release prior writes
        atomicAdd((int*)&g_sync[j], 1);
        while (g_sync[j] < target) { }
        __threadfence();                       // acquire peers' writes
    }
    __syncthreads();
}

// ---------------- init: flags, counters, cluster copy, ||w||^2 ----------------
__global__ void init_kernel(const float* __restrict__ W, const float* __restrict__ C0) {
    int gid = blockIdx.x * blockDim.x + threadIdx.x;   // NROWS threads
    if (gid == 0) { g_done = 0; g_commit = 1; g_sync[0] = 0; g_sync[1] = 0; g_sync[2] = 0; }
    if (gid < KC * DIM) g_clusters[gid] = C0[gid];
    const float4* p = (const float4*)(W + (size_t)gid * DIM);
    float s = 0.f;
#pragma unroll
    for (int j = 0; j < 16; j++) {
        float4 v = p[j];
        s += v.x * v.x + v.y * v.y + v.z * v.z + v.w * v.w;
    }
    g_wsq[gid] = s;
}

// ---------------- fully fused iteration kernel ----------------
// phase 1: tensor-core GEMM1 -> softmax -> GEMM2 partials  (all blocks)
// gsync0 -> phase 3: per-k reduction of partials (blocks 0..63)
// gsync1 -> phase 4: convergence decision (block 0)
// gsync2 -> phase 5: cluster commit + g_prev (blocks 0..63)
__global__ __launch_bounds__(TPB, 1) void iter_fused(int it, const float* __restrict__ W) {
    if (g_done) return;
    extern __shared__ float sm[];
    float* cl    = sm;            // [64][68] clusters (tf32-rounded), row-major [k][d]
    float* csq   = sm + 4352;     // [64] exact ||c||^2
    float* wrow  = sm + 4416;     // [128][68] W tile (GEMM1 A)
    float* wrow2 = sm + 13120;    // [128][72] W tile + ones col (GEMM2 B)
    float* att   = sm + 22336;    // [128][72] attn tile (GEMM2 A)
    float* wsqs  = sm + 31552;    // [128]

    const int tid = threadIdx.x;
    const int lane = tid & 31, wid = tid >> 5;
    const int gid = lane >> 2, tig = lane & 3;
    const int m1 = wid * 16;            // GEMM1 row offset
    const int m2 = (wid & 3) * 16;      // GEMM2 kc offset
    const int rh = (wid >> 2) * 64;     // GEMM2 row-half offset
    const int target = (it + 1) * (int)gridDim.x;

    for (int i = tid; i < KC * DIM; i += TPB)
        cl[(i >> 6) * 68 + (i & 63)] = __uint_as_float(f2t(g_clusters[i]));
    if (tid < KC) {
        float s = 0.f;
#pragma unroll
        for (int d = 0; d < DIM; d++) { float v = g_clusters[tid * DIM + d]; s += v * v; }
        csq[tid] = s;
    }
    __syncthreads();
    float csqL[8], csqR[8];
#pragma unroll
    for (int j = 0; j < 8; j++) { csqL[j] = csq[8 * j + 2 * tig]; csqR[j] = csq[8 * j + 2 * tig + 1]; }

    float c2[9][4];
#pragma unroll
    for (int j = 0; j < 9; j++) { c2[j][0] = c2[j][1] = c2[j][2] = c2[j][3] = 0.f; }

    for (int tile = blockIdx.x; tile < NT; tile += gridDim.x) {
        const size_t row0 = (size_t)tile * MT;
        __syncthreads();
        for (int i = tid * 4; i < MT * DIM; i += TPB * 4) {
            float4 v = *(const float4*)(W + row0 * DIM + i);
            v.x = __uint_as_float(f2t(v.x));
            v.y = __uint_as_float(f2t(v.y));
            v.z = __uint_as_float(f2t(v.z));
            v.w = __uint_as_float(f2t(v.w));
            int r = i >> 6, d = i & 63;
            *(float4*)(wrow + r * 68 + d) = v;
            *(float4*)(wrow2 + r * 72 + d) = v;
        }
        if (tid < MT) { wrow2[tid * 72 + 64] = 1.0f; wsqs[tid] = g_wsq[row0 + tid]; }
        __syncthreads();

        // ---- GEMM1: C1[row][kc] = W * C^T ----
        float c1[8][4];
#pragma unroll
        for (int j = 0; j < 8; j++) { c1[j][0] = c1[j][1] = c1[j][2] = c1[j][3] = 0.f; }
        const float* Ab = wrow + (m1 + gid) * 68 + tig;
#pragma unroll 4
        for (int s = 0; s < 8; s++) {
            const int k0 = 8 * s;
            uint32_t a0 = BITS(Ab[k0]);
            uint32_t a1 = BITS(Ab[8 * 68 + k0]);
            uint32_t a2 = BITS(Ab[k0 + 4]);
            uint32_t a3 = BITS(Ab[8 * 68 + k0 + 4]);
            const float* Bb = cl + gid * 68 + k0 + tig;
#pragma unroll
            for (int j = 0; j < 8; j++) {
                uint32_t b0 = BITS(Bb[j * 8 * 68]);
                uint32_t b1 = BITS(Bb[j * 8 * 68 + 4]);
                mma8(c1[j], a0, a1, a2, a3, b0, b1);
            }
        }

        // ---- softmax in registers ----
        float wsA = wsqs[m1 + gid], wsB = wsqs[m1 + gid + 8];
        float eA[16], eB[16], mnA = 3.4e38f, mnB = 3.4e38f;
#pragma unroll
        for (int j = 0; j < 8; j++) {
            float dA0 = sqrtf(fmaxf(wsA + csqL[j] - 2.f * c1[j][0], 0.f));
            float dA1 = sqrtf(fmaxf(wsA + csqR[j] - 2.f * c1[j][1], 0.f));
            float dB0 = sqrtf(fmaxf(wsB + csqL[j] - 2.f * c1[j][2], 0.f));
            float dB1 = sqrtf(fmaxf(wsB + csqR[j] - 2.f * c1[j][3], 0.f));
            eA[2 * j] = dA0; eA[2 * j + 1] = dA1;
            eB[2 * j] = dB0; eB[2 * j + 1] = dB1;
            mnA = fminf(mnA, fminf(dA0, dA1));
            mnB = fminf(mnB, fminf(dB0, dB1));
        }
        mnA = fminf(mnA, __shfl_xor_sync(0xffffffffu, mnA, 1));
        mnA = fminf(mnA, __shfl_xor_sync(0xffffffffu, mnA, 2));
        mnB = fminf(mnB, __shfl_xor_sync(0xffffffffu, mnB, 1));
        mnB = fminf(mnB, __shfl_xor_sync(0xffffffffu, mnB, 2));
        float sA = 0.f, sB = 0.f;
#pragma unroll
        for (int j = 0; j < 16; j++) {
            eA[j] = __expf(mnA - eA[j]); sA += eA[j];
            eB[j] = __expf(mnB - eB[j]); sB += eB[j];
        }
        sA += __shfl_xor_sync(0xffffffffu, sA, 1);
        sA += __shfl_xor_sync(0xffffffffu, sA, 2);
        sB += __shfl_xor_sync(0xffffffffu, sB, 1);
        sB += __shfl_xor_sync(0xffffffffu, sB, 2);
        float iA = 1.f / sA, iB = 1.f / sB;
        float* wA = att + (m1 + gid) * 72 + 2 * tig;
        float* wB = att + (m1 + gid + 8) * 72 + 2 * tig;
#pragma unroll
        for (int j = 0; j < 8; j++) {
            float2 vA = make_float2(__uint_as_float(f2t(eA[2 * j] * iA)),
                                    __uint_as_float(f2t(eA[2 * j + 1] * iA)));
            float2 vB = make_float2(__uint_as_float(f2t(eB[2 * j] * iB)),
                                    __uint_as_float(f2t(eB[2 * j + 1] * iB)));
            *(float2*)(wA + 8 * j) = vA;
            *(float2*)(wB + 8 * j) = vB;
        }
        __syncthreads();

        // ---- GEMM2: C2[kc][d] += attn^T * W  (9th n-frag vs ones col = colsum) ----
        const float* A2 = att + (rh + tig) * 72 + m2 + gid;
        const float* B2 = wrow2 + (rh + tig) * 72 + gid;
#pragma unroll 4
        for (int s = 0; s < 8; s++) {
            const int o = s * 8 * 72;
            uint32_t a0 = BITS(A2[o]);
            uint32_t a1 = BITS(A2[o + 8]);
            uint32_t a2 = BITS(A2[o + 4 * 72]);
            uint32_t a3 = BITS(A2[o + 4 * 72 + 8]);
#pragma unroll
            for (int j = 0; j < 9; j++) {
                uint32_t b0 = BITS(B2[o + 8 * j]);
                uint32_t b1 = BITS(B2[o + 4 * 72 + 8 * j]);
                mma8(c2[j], a0, a1, a2, a3, b0, b1);
            }
        }
    }

    // ---- phase 2: per-(block, row-half) partials ----
    {
        float* P = g_part + (size_t)(blockIdx.x * 2 + (wid >> 2)) * PSTR;
#pragma unroll
        for (int j = 0; j < 8; j++) {
            *(float2*)(P + (m2 + gid) * 68 + 8 * j + 2 * tig) = make_float2(c2[j][0], c2[j][1]);
            *(float2*)(P + (m2 + gid + 8) * 68 + 8 * j + 2 * tig) = make_float2(c2[j][2], c2[j][3]);
        }
        if (tig == 0) {
            P[(m2 + gid) * 68 + 64] = c2[8][0];
            P[(m2 + gid + 8) * 68 + 64] = c2[8][2];
        }
    }

    gsync(0, target);

    // ---- phase 3: blocks 0..63 reduce partials for their k ----
    float nv = 0.f, ov = 0.f;
    const int kblk = blockIdx.x;
    {
        float* r_num = sm;          // [4][64]
        float* r_den = sm + 256;    // [4]
        float* s_nrm = sm + 264;    // [2]
        if (kblk < 64) {
            const int q = tid >> 6, d = tid & 63;
            const int nslots = (int)gridDim.x * 2;
            float s = 0.f, sden = 0.f;
            const float* base = g_part + kblk * 68;
            for (int b = q; b < nslots; b += 4) {
                const float* P = base + (size_t)b * PSTR;
                s += P[d];
                if (d == 0) sden += P[64];
            }
            r_num[q * 64 + d] = s;
            if (d == 0) r_den[q] = sden;
        }
        __syncthreads();
        if (kblk < 64 && tid < 64) {
            float num = (r_num[tid] + r_num[64 + tid]) + (r_num[128 + tid] + r_num[192 + tid]);
            float den = (r_den[0] + r_den[1]) + (r_den[2] + r_den[3]);
            nv = num / den;
            ov = g_clusters[kblk * 64 + tid];
            float x = (nv - ov) * (nv - ov);
#pragma unroll
            for (int o = 16; o > 0; o >>= 1) x += __shfl_xor_sync(0xffffffffu, x, o);
            if ((tid & 31) == 0) s_nrm[tid >> 5] = x;
        }
        __syncthreads();
        if (kblk < 64 && tid == 0) g_normk[kblk] = s_nrm[0] + s_nrm[1];
    }

    gsync(1, target);

    // ---- phase 4: block 0 decides convergence ----
    if (kblk == 0 && tid == 0) {
        float t = 0.f;
        for (int k = 0; k < 64; k++) t += g_normk[k];
        int conv = (sqrtf(t) <= 1e-4f) ? 1 : 0;
        g_commit = conv ? 0 : 1;
        if (conv) g_done = 1;      // freeze: clusters NOT updated
    }

    gsync(2, target);

    // ---- phase 5: commit clusters + save g_prev ----
    if (kblk < 64 && tid < 64) {
        int cm = g_commit;
        g_prev[kblk * 64 + tid] = ov;
        g_clusters[kblk * 64 + tid] = cm ? nv : ov;
    }
}

// ---------------- fused final: attn (fp32, vs g_prev) + compressed + clusters ----------------
__global__ __launch_bounds__(TPB) void final_fused(const float* __restrict__ W,
                                                   float* __restrict__ attn_out,
                                                   float* __restrict__ comp,
                                                   float* __restrict__ clus_out) {
    extern __shared__ float sm[];
    float* csT = sm;                 // [64][68] g_prev transposed [d][k]
    float* wsT = sm + 4352;          // [64][68] W tile transposed [d][r]
    float* att = sm + 8704;          // [64][68] d2, then attn
    float* cs  = sm + 13056;         // [64][64] g_clusters row-major
    float* csq = sm + 17152;         // [64]
    float* wsq = sm + 17216;         // [64]
    const int tid = threadIdx.x;
    const int tx = tid & 15, ty = tid >> 4;
    const int i0 = ty * 4;

    for (int i = tid; i < KC * DIM; i += TPB) {
        float pv = g_prev[i];
        csT[(i & 63) * 68 + (i >> 6)] = pv;
        float cv = g_clusters[i];
        cs[i] = cv;
        if (blockIdx.x == 0) clus_out[i] = cv;
    }
    __syncthreads();
    if (tid < KC) {
        float s = 0.f;
#pragma unroll
        for (int d = 0; d < DIM; d++) { float v = csT[d * 68 + tid]; s += v * v; }
        csq[tid] = s;
    }
    const int row0 = blockIdx.x * 64;
    for (int i = tid * 4; i < 64 * DIM; i += TPB * 4) {
        float4 v = *(const float4*)(W + (size_t)row0 * DIM + i);
        int r = i >> 6, d = i & 63;
        wsT[(d + 0) * 68 + r] = v.x;
        wsT[(d + 1) * 68 + r] = v.y;
        wsT[(d + 2) * 68 + r] = v.z;
        wsT[(d + 3) * 68 + r] = v.w;
    }
    if (tid < 64) wsq[tid] = g_wsq[row0 + tid];
    __syncthreads();

    // GEMM1 (fp32): d2 = ||w||^2 + ||c||^2 - 2 W C_prev^T
    {
        const int k0 = tx * 4;
        float acc[4][4];
#pragma unroll
        for (int a = 0; a < 4; a++)
#pragma unroll
            for (int b = 0; b < 4; b++) acc[a][b] = 0.f;
#pragma unroll 8
        for (int d = 0; d < DIM; d++) {
            float4 av = *(float4*)(wsT + d * 68 + i0);
            float4 bv = *(float4*)(csT + d * 68 + k0);
            float a[4] = {av.x, av.y, av.z, av.w};
            float b[4] = {bv.x, bv.y, bv.z, bv.w};
#pragma unroll
            for (int ii = 0; ii < 4; ii++)
#pragma unroll
                for (int kk = 0; kk < 4; kk++) acc[ii][kk] += a[ii] * b[kk];
        }
#pragma unroll
        for (int ii = 0; ii < 4; ii++) {
            float w2 = wsq[i0 + ii];
            float4 v;
            v.x = w2 + csq[k0 + 0] - 2.f * acc[ii][0];
            v.y = w2 + csq[k0 + 1] - 2.f * acc[ii][1];
            v.z = w2 + csq[k0 + 2] - 2.f * acc[ii][2];
            v.w = w2 + csq[k0 + 3] - 2.f * acc[ii][3];
            *(float4*)(att + (i0 + ii) * 68 + k0) = v;
        }
    }
    __syncthreads();

    // softmax rows -> attn (smem row-major + gmem)
    {
        const int row = tid >> 2, q = tid & 3;
        float e[16];
        float mn = 3.4e38f;
#pragma unroll
        for (int j = 0; j < 16; j++) {
            float d2v = att[row * 68 + q * 16 + j];
            float dv = sqrtf(fmaxf(d2v, 0.f));
            e[j] = dv;
            mn = fminf(mn, dv);
        }
        mn = fminf(mn, __shfl_xor_sync(0xffffffffu, mn, 1));
        mn = fminf(mn, __shfl_xor_sync(0xffffffffu, mn, 2));
        float s = 0.f;
#pragma unroll
        for (int j = 0; j < 16; j++) {
            float ex = __expf(mn - e[j]);
            e[j] = ex;
            s += ex;
        }
        s += __shfl_xor_sync(0xffffffffu, s, 1);
        s += __shfl_xor_sync(0xffffffffu, s, 2);
        float inv = 1.f / s;
        float* ga = attn_out + (size_t)(row0 + row) * KC + q * 16;
#pragma unroll
        for (int j4 = 0; j4 < 4; j4++) {
            float4 v;
            v.x = e[j4 * 4 + 0] * inv; v.y = e[j4 * 4 + 1] * inv;
            v.z = e[j4 * 4 + 2] * inv; v.w = e[j4 * 4 + 3] * inv;
            *(float4*)(att + row * 68 + q * 16 + j4 * 4) = v;
            *(float4*)(ga + j4 * 4) = v;
        }
    }
    __syncthreads();

    // GEMM3 (fp32): comp = attn @ clusters  (A scalar broadcast loads, B float4)
    {
        const int d0 = tx * 4;
        float acc[4][4];
#pragma unroll
        for (int a = 0; a < 4; a++)
#pragma unroll
            for (int b = 0; b < 4; b++) acc[a][b] = 0.f;
#pragma unroll 8
        for (int k = 0; k < KC; k++) {
            float a0 = att[(i0 + 0) * 68 + k];
            float a1 = att[(i0 + 1) * 68 + k];
            float a2 = att[(i0 + 2) * 68 + k];
            float a3 = att[(i0 + 3) * 68 + k];
            float4 bv = *(float4*)(cs + k * 64 + d0);
            acc[0][0] += a0 * bv.x; acc[0][1] += a0 * bv.y; acc[0][2] += a0 * bv.z; acc[0][3] += a0 * bv.w;
            acc[1][0] += a1 * bv.x; acc[1][1] += a1 * bv.y; acc[1][2] += a1 * bv.z; acc[1][3] += a1 * bv.w;
            acc[2][0] += a2 * bv.x; acc[2][1] += a2 * bv.y; acc[2][2] += a2 * bv.z; acc[2][3] += a2 * bv.w;
            acc[3][0] += a3 * bv.x; acc[3][1] += a3 * bv.y; acc[3][2] += a3 * bv.z; acc[3][3] += a3 * bv.w;
        }
#pragma unroll
        for (int ii = 0; ii < 4; ii++) {
            float4 v = {acc[ii][0], acc[ii][1], acc[ii][2], acc[ii][3]};
            *(float4*)(comp + (size_t)(row0 + i0 + ii) * DIM + d0) = v;
        }
    }
}

// ---------------- launch ----------------
extern "C" void kernel_launch(void* const* d_in, const int* in_sizes, int n_in,
                              void* d_out, int out_size) {
    const float* W  = (const float*)d_in[0];
    const float* C0 = (const float*)d_in[1];
    float* out  = (float*)d_out;
    float* comp = out;                                    // [N, D]
    float* clus = out + (size_t)NROWS * DIM;              // [K, D]
    float* attn = clus + (size_t)KC * DIM;                // [N, K]

    int sms = 0;
    cudaDeviceGetAttribute(&sms, cudaDevAttrMultiProcessorCount, 0);
    if (sms <= 0 || sms > MAXGRID) sms = MAXGRID;

    const int smem_iter  = 31680 * (int)sizeof(float);    // 126720 B -> occ 1, all resident
    const int smem_final = 17280 * (int)sizeof(float);    // 69120 B
    cudaFuncSetAttribute(iter_fused, cudaFuncAttributeMaxDynamicSharedMemorySize, smem_iter);
    cudaFuncSetAttribute(final_fused, cudaFuncAttributeMaxDynamicSharedMemorySize, smem_final);

    init_kernel<<<NROWS / TPB, TPB>>>(W, C0);
    for (int it = 0; it < ITERS; it++)
        iter_fused<<<sms, TPB, smem_iter>>>(it, W);
    final_fused<<<NROWS / 64, TPB, smem_final>>>(W, attn, comp, clus);
}

// round 6
// speedup vs baseline: 2.0667x; 1.0091x over previous
#include <cuda_runtime.h>
#include <math.h>
#include <stdint.h>

#define NROWS 131072
#define DIM 64
#define KC 64
#define ITERS 10
#define TPB 256
#define MT 128                    // rows per tile in mma iteration kernel
#define NT (NROWS / MT)           // 1024 tiles
#define MAXGRID 148
#define PSTR (64 * 68)            // 4352 floats per partial slot

// ---------------- device globals (no cudaMalloc allowed) ----------------
__device__ float g_clusters[KC * DIM];
__device__ float g_prev[KC * DIM];          // clusters used by last active iteration
__device__ float g_S_unused;                // (kept out: reduction now in-kernel)
__device__ float g_part[(size_t)(2 * MAXGRID) * PSTR];
__device__ float g_normk[KC];
__device__ float g_wsq[NROWS];
__device__ int   g_done;
__device__ int   g_commit;
__device__ volatile int g_sync[3];

// ---------------- helpers ----------------
__device__ __forceinline__ uint32_t f2t(float x) {
    uint32_t u;
    asm("cvt.rna.tf32.f32 %0, %1;" : "=r"(u) : "f"(x));
    return u;
}
__device__ __forceinline__ void mma8(float c[4], uint32_t a0, uint32_t a1, uint32_t a2,
                                     uint32_t a3, uint32_t b0, uint32_t b1) {
    asm volatile(
        "mma.sync.aligned.m16n8k8.row.col.f32.tf32.tf32.f32 "
        "{%0,%1,%2,%3},{%4,%5,%6,%7},{%8,%9},{%0,%1,%2,%3};"
        : "+f"(c[0]), "+f"(c[1]), "+f"(c[2]), "+f"(c[3])
        : "r"(a0), "r"(a1), "r"(a2), "r"(a3), "r"(b0), "r"(b1));
}
#define BITS(x) (__float_as_uint(x))

// deterministic grid-wide sync: monotonic counters, per-launch target
__device__ __forceinline__ void gsync(int j, int target) {
    __syncthreads();
    if (threadIdx.x == 0) {
        __threadfence();                       // release prior writes
        atomicAdd((int*)&g_sync[j], 1);
        while (g_sync[j] < target) { }
        __threadfence();                       // acquire peers' writes
    }
    __syncthreads();
}

// ---------------- init: flags, counters, cluster copy, ||w||^2 ----------------
__global__ void init_kernel(const float* __restrict__ W, const float* __restrict__ C0) {
    int gid = blockIdx.x * blockDim.x + threadIdx.x;   // NROWS threads
    if (gid == 0) { g_done = 0; g_commit = 1; g_sync[0] = 0; g_sync[1] = 0; g_sync[2] = 0; }
    if (gid < KC * DIM) g_clusters[gid] = C0[gid];
    const float4* p = (const float4*)(W + (size_t)gid * DIM);
    float s = 0.f;
#pragma unroll
    for (int j = 0; j < 16; j++) {
        float4 v = p[j];
        s += v.x * v.x + v.y * v.y + v.z * v.z + v.w * v.w;
    }
    g_wsq[gid] = s;
}

// ---------------- fully fused iteration kernel ----------------
// phase 1: tensor-core GEMM1 -> softmax -> GEMM2 partials  (all blocks)
// gsync0 -> phase 3: per-k reduction of partials (blocks 0..63)
// gsync1 -> phase 4: convergence decision (block 0)
// gsync2 -> phase 5: cluster commit + g_prev (blocks 0..63)
__global__ __launch_bounds__(TPB, 1) void iter_fused(int it, const float* __restrict__ W) {
    if (g_done) return;
    extern __shared__ float sm[];
    float* cl    = sm;            // [64][68] clusters (tf32-rounded), row-major [k][d]
    float* csq   = sm + 4352;     // [64] exact ||c||^2
    float* wrow  = sm + 4416;     // [128][68] W tile (GEMM1 A)
    float* wrow2 = sm + 13120;    // [128][72] W tile + ones col (GEMM2 B)
    float* att   = sm + 22336;    // [128][72] attn tile (GEMM2 A)
    float* wsqs  = sm + 31552;    // [128]

    const int tid = threadIdx.x;
    const int lane = tid & 31, wid = tid >> 5;
    const int gid = lane >> 2, tig = lane & 3;
    const int m1 = wid * 16;            // GEMM1 row offset
    const int m2 = (wid & 3) * 16;      // GEMM2 kc offset
    const int rh = (wid >> 2) * 64;     // GEMM2 row-half offset
    const int target = (it + 1) * (int)gridDim.x;

    for (int i = tid; i < KC * DIM; i += TPB)
        cl[(i >> 6) * 68 + (i & 63)] = __uint_as_float(f2t(g_clusters[i]));
    if (tid < KC) {
        float s = 0.f;
#pragma unroll
        for (int d = 0; d < DIM; d++) { float v = g_clusters[tid * DIM + d]; s += v * v; }
        csq[tid] = s;
    }
    __syncthreads();
    float csqL[8], csqR[8];
#pragma unroll
    for (int j = 0; j < 8; j++) { csqL[j] = csq[8 * j + 2 * tig]; csqR[j] = csq[8 * j + 2 * tig + 1]; }

    float c2[9][4];
#pragma unroll
    for (int j = 0; j < 9; j++) { c2[j][0] = c2[j][1] = c2[j][2] = c2[j][3] = 0.f; }

    for (int tile = blockIdx.x; tile < NT; tile += gridDim.x) {
        const size_t row0 = (size_t)tile * MT;
        __syncthreads();
        for (int i = tid * 4; i < MT * DIM; i += TPB * 4) {
            float4 v = *(const float4*)(W + row0 * DIM + i);
            v.x = __uint_as_float(f2t(v.x));
            v.y = __uint_as_float(f2t(v.y));
            v.z = __uint_as_float(f2t(v.z));
            v.w = __uint_as_float(f2t(v.w));
            int r = i >> 6, d = i & 63;
            *(float4*)(wrow + r * 68 + d) = v;
            *(float4*)(wrow2 + r * 72 + d) = v;
        }
        if (tid < MT) { wrow2[tid * 72 + 64] = 1.0f; wsqs[tid] = g_wsq[row0 + tid]; }
        __syncthreads();

        // ---- GEMM1: C1[row][kc] = W * C^T ----
        float c1[8][4];
#pragma unroll
        for (int j = 0; j < 8; j++) { c1[j][0] = c1[j][1] = c1[j][2] = c1[j][3] = 0.f; }
        const float* Ab = wrow + (m1 + gid) * 68 + tig;
#pragma unroll 4
        for (int s = 0; s < 8; s++) {
            const int k0 = 8 * s;
            uint32_t a0 = BITS(Ab[k0]);
            uint32_t a1 = BITS(Ab[8 * 68 + k0]);
            uint32_t a2 = BITS(Ab[k0 + 4]);
            uint32_t a3 = BITS(Ab[8 * 68 + k0 + 4]);
            const float* Bb = cl + gid * 68 + k0 + tig;
#pragma unroll
            for (int j = 0; j < 8; j++) {
                uint32_t b0 = BITS(Bb[j * 8 * 68]);
                uint32_t b1 = BITS(Bb[j * 8 * 68 + 4]);
                mma8(c1[j], a0, a1, a2, a3, b0, b1);
            }
        }

        // ---- softmax in registers ----
        float wsA = wsqs[m1 + gid], wsB = wsqs[m1 + gid + 8];
        float eA[16], eB[16], mnA = 3.4e38f, mnB = 3.4e38f;
#pragma unroll
        for (int j = 0; j < 8; j++) {
            float dA0 = sqrtf(fmaxf(wsA + csqL[j] - 2.f * c1[j][0], 0.f));
            float dA1 = sqrtf(fmaxf(wsA + csqR[j] - 2.f * c1[j][1], 0.f));
            float dB0 = sqrtf(fmaxf(wsB + csqL[j] - 2.f * c1[j][2], 0.f));
            float dB1 = sqrtf(fmaxf(wsB + csqR[j] - 2.f * c1[j][3], 0.f));
            eA[2 * j] = dA0; eA[2 * j + 1] = dA1;
            eB[2 * j] = dB0; eB[2 * j + 1] = dB1;
            mnA = fminf(mnA, fminf(dA0, dA1));
            mnB = fminf(mnB, fminf(dB0, dB1));
        }
        mnA = fminf(mnA, __shfl_xor_sync(0xffffffffu, mnA, 1));
        mnA = fminf(mnA, __shfl_xor_sync(0xffffffffu, mnA, 2));
        mnB = fminf(mnB, __shfl_xor_sync(0xffffffffu, mnB, 1));
        mnB = fminf(mnB, __shfl_xor_sync(0xffffffffu, mnB, 2));
        float sA = 0.f, sB = 0.f;
#pragma unroll
        for (int j = 0; j < 16; j++) {
            eA[j] = __expf(mnA - eA[j]); sA += eA[j];
            eB[j] = __expf(mnB - eB[j]); sB += eB[j];
        }
        sA += __shfl_xor_sync(0xffffffffu, sA, 1);
        sA += __shfl_xor_sync(0xffffffffu, sA, 2);
        sB += __shfl_xor_sync(0xffffffffu, sB, 1);
        sB += __shfl_xor_sync(0xffffffffu, sB, 2);
        float iA = 1.f / sA, iB = 1.f / sB;
        float* wA = att + (m1 + gid) * 72 + 2 * tig;
        float* wB = att + (m1 + gid + 8) * 72 + 2 * tig;
#pragma unroll
        for (int j = 0; j < 8; j++) {
            float2 vA = make_float2(__uint_as_float(f2t(eA[2 * j] * iA)),
                                    __uint_as_float(f2t(eA[2 * j + 1] * iA)));
            float2 vB = make_float2(__uint_as_float(f2t(eB[2 * j] * iB)),
                                    __uint_as_float(f2t(eB[2 * j + 1] * iB)));
            *(float2*)(wA + 8 * j) = vA;
            *(float2*)(wB + 8 * j) = vB;
        }
        __syncthreads();

        // ---- GEMM2: C2[kc][d] += attn^T * W  (9th n-frag vs ones col = colsum) ----
        const float* A2 = att + (rh + tig) * 72 + m2 + gid;
        const float* B2 = wrow2 + (rh + tig) * 72 + gid;
#pragma unroll 4
        for (int s = 0; s < 8; s++) {
            const int o = s * 8 * 72;
            uint32_t a0 = BITS(A2[o]);
            uint32_t a1 = BITS(A2[o + 8]);
            uint32_t a2 = BITS(A2[o + 4 * 72]);
            uint32_t a3 = BITS(A2[o + 4 * 72 + 8]);
#pragma unroll
            for (int j = 0; j < 9; j++) {
                uint32_t b0 = BITS(B2[o + 8 * j]);
                uint32_t b1 = BITS(B2[o + 4 * 72 + 8 * j]);
                mma8(c2[j], a0, a1, a2, a3, b0, b1);
            }
        }
    }

    // ---- phase 2: per-(block, row-half) partials ----
    {
        float* P = g_part + (size_t)(blockIdx.x * 2 + (wid >> 2)) * PSTR;
#pragma unroll
        for (int j = 0; j < 8; j++) {
            *(float2*)(P + (m2 + gid) * 68 + 8 * j + 2 * tig) = make_float2(c2[j][0], c2[j][1]);
            *(float2*)(P + (m2 + gid + 8) * 68 + 8 * j + 2 * tig) = make_float2(c2[j][2], c2[j][3]);
        }
        if (tig == 0) {
            P[(m2 + gid) * 68 + 64] = c2[8][0];
            P[(m2 + gid + 8) * 68 + 64] = c2[8][2];
        }
    }

    gsync(0, target);

    // ---- phase 3: blocks 0..63 reduce partials for their k ----
    float nv = 0.f, ov = 0.f;
    const int kblk = blockIdx.x;
    {
        float* r_num = sm;          // [4][64]
        float* r_den = sm + 256;    // [4]
        float* s_nrm = sm + 264;    // [2]
        if (kblk < 64) {
            const int q = tid >> 6, d = tid & 63;
            const int nslots = (int)gridDim.x * 2;
            float s = 0.f, sden = 0.f;
            const float* base = g_part + kblk * 68;
            for (int b = q; b < nslots; b += 4) {
                const float* P = base + (size_t)b * PSTR;
                s += P[d];
                if (d == 0) sden += P[64];
            }
            r_num[q * 64 + d] = s;
            if (d == 0) r_den[q] = sden;
        }
        __syncthreads();
        if (kblk < 64 && tid < 64) {
            float num = (r_num[tid] + r_num[64 + tid]) + (r_num[128 + tid] + r_num[192 + tid]);
            float den = (r_den[0] + r_den[1]) + (r_den[2] + r_den[3]);
            nv = num / den;
            ov = g_clusters[kblk * 64 + tid];
            float x = (nv - ov) * (nv - ov);
#pragma unroll
            for (int o = 16; o > 0; o >>= 1) x += __shfl_xor_sync(0xffffffffu, x, o);
            if ((tid & 31) == 0) s_nrm[tid >> 5] = x;
        }
        __syncthreads();
        if (kblk < 64 && tid == 0) g_normk[kblk] = s_nrm[0] + s_nrm[1];
    }

    gsync(1, target);

    // ---- phase 4: block 0 decides convergence ----
    if (kblk == 0 && tid == 0) {
        float t = 0.f;
        for (int k = 0; k < 64; k++) t += g_normk[k];
        int conv = (sqrtf(t) <= 1e-4f) ? 1 : 0;
        g_commit = conv ? 0 : 1;
        if (conv) g_done = 1;      // freeze: clusters NOT updated
    }

    gsync(2, target);

    // ---- phase 5: commit clusters + save g_prev ----
    if (kblk < 64 && tid < 64) {
        int cm = g_commit;
        g_prev[kblk * 64 + tid] = ov;
        g_clusters[kblk * 64 + tid] = cm ? nv : ov;
    }
}

// ---------------- fused final: attn (fp32, vs g_prev) + compressed + clusters ----------------
__global__ __launch_bounds__(TPB) void final_fused(const float* __restrict__ W,
                                                   float* __restrict__ attn_out,
                                                   float* __restrict__ comp,
                                                   float* __restrict__ clus_out) {
    extern __shared__ float sm[];
    float* csT = sm;                 // [64][68] g_prev transposed [d][k]
    float* wsT = sm + 4352;          // [64][68] W tile transposed [d][r]
    float* att = sm + 8704;          // [64][68] d2, then attn
    float* cs  = sm + 13056;         // [64][64] g_clusters row-major
    float* csq = sm + 17152;         // [64]
    float* wsq = sm + 17216;         // [64]
    const int tid = threadIdx.x;
    const int tx = tid & 15, ty = tid >> 4;
    const int i0 = ty * 4;

    for (int i = tid; i < KC * DIM; i += TPB) {
        float pv = g_prev[i];
        csT[(i & 63) * 68 + (i >> 6)] = pv;
        float cv = g_clusters[i];
        cs[i] = cv;
        if (blockIdx.x == 0) clus_out[i] = cv;
    }
    __syncthreads();
    if (tid < KC) {
        float s = 0.f;
#pragma unroll
        for (int d = 0; d < DIM; d++) { float v = csT[d * 68 + tid]; s += v * v; }
        csq[tid] = s;
    }
    const int row0 = blockIdx.x * 64;
    for (int i = tid * 4; i < 64 * DIM; i += TPB * 4) {
        float4 v = *(const float4*)(W + (size_t)row0 * DIM + i);
        int r = i >> 6, d = i & 63;
        wsT[(d + 0) * 68 + r] = v.x;
        wsT[(d + 1) * 68 + r] = v.y;
        wsT[(d + 2) * 68 + r] = v.z;
        wsT[(d + 3) * 68 + r] = v.w;
    }
    if (tid < 64) wsq[tid] = g_wsq[row0 + tid];
    __syncthreads();

    // GEMM1 (fp32): d2 = ||w||^2 + ||c||^2 - 2 W C_prev^T
    {
        const int k0 = tx * 4;
        float acc[4][4];
#pragma unroll
        for (int a = 0; a < 4; a++)
#pragma unroll
            for (int b = 0; b < 4; b++) acc[a][b] = 0.f;
#pragma unroll 8
        for (int d = 0; d < DIM; d++) {
            float4 av = *(float4*)(wsT + d * 68 + i0);
            float4 bv = *(float4*)(csT + d * 68 + k0);
            float a[4] = {av.x, av.y, av.z, av.w};
            float b[4] = {bv.x, bv.y, bv.z, bv.w};
#pragma unroll
            for (int ii = 0; ii < 4; ii++)
#pragma unroll
                for (int kk = 0; kk < 4; kk++) acc[ii][kk] += a[ii] * b[kk];
        }
#pragma unroll
        for (int ii = 0; ii < 4; ii++) {
            float w2 = wsq[i0 + ii];
            float4 v;
            v.x = w2 + csq[k0 + 0] - 2.f * acc[ii][0];
            v.y = w2 + csq[k0 + 1] - 2.f * acc[ii][1];
            v.z = w2 + csq[k0 + 2] - 2.f * acc[ii][2];
            v.w = w2 + csq[k0 + 3] - 2.f * acc[ii][3];
            *(float4*)(att + (i0 + ii) * 68 + k0) = v;
        }
    }
    __syncthreads();

    // softmax rows -> attn (smem row-major + gmem)
    {
        const int row = tid >> 2, q = tid & 3;
        float e[16];
        float mn = 3.4e38f;
#pragma unroll
        for (int j = 0; j < 16; j++) {
            float d2v = att[row * 68 + q * 16 + j];
            float dv = sqrtf(fmaxf(d2v, 0.f));
            e[j] = dv;
            mn = fminf(mn, dv);
        }
        mn = fminf(mn, __shfl_xor_sync(0xffffffffu, mn, 1));
        mn = fminf(mn, __shfl_xor_sync(0xffffffffu, mn, 2));
        float s = 0.f;
#pragma unroll
        for (int j = 0; j < 16; j++) {
            float ex = __expf(mn - e[j]);
            e[j] = ex;
            s += ex;
        }
        s += __shfl_xor_sync(0xffffffffu, s, 1);
        s += __shfl_xor_sync(0xffffffffu, s, 2);
        float inv = 1.f / s;
        float* ga = attn_out + (size_t)(row0 + row) * KC + q * 16;
#pragma unroll
        for (int j4 = 0; j4 < 4; j4++) {
            float4 v;
            v.x = e[j4 * 4 + 0] * inv; v.y = e[j4 * 4 + 1] * inv;
            v.z = e[j4 * 4 + 2] * inv; v.w = e[j4 * 4 + 3] * inv;
            *(float4*)(att + row * 68 + q * 16 + j4 * 4) = v;
            *(float4*)(ga + j4 * 4) = v;
        }
    }
    __syncthreads();

    // GEMM3 (fp32): comp = attn @ clusters  (A scalar broadcast loads, B float4)
    {
        const int d0 = tx * 4;
        float acc[4][4];
#pragma unroll
        for (int a = 0; a < 4; a++)
#pragma unroll
            for (int b = 0; b < 4; b++) acc[a][b] = 0.f;
#pragma unroll 8
        for (int k = 0; k < KC; k++) {
            float a0 = att[(i0 + 0) * 68 + k];
            float a1 = att[(i0 + 1) * 68 + k];
            float a2 = att[(i0 + 2) * 68 + k];
            float a3 = att[(i0 + 3) * 68 + k];
            float4 bv = *(float4*)(cs + k * 64 + d0);
            acc[0][0] += a0 * bv.x; acc[0][1] += a0 * bv.y; acc[0][2] += a0 * bv.z; acc[0][3] += a0 * bv.w;
            acc[1][0] += a1 * bv.x; acc[1][1] += a1 * bv.y; acc[1][2] += a1 * bv.z; acc[1][3] += a1 * bv.w;
            acc[2][0] += a2 * bv.x; acc[2][1] += a2 * bv.y; acc[2][2] += a2 * bv.z; acc[2][3] += a2 * bv.w;
            acc[3][0] += a3 * bv.x; acc[3][1] += a3 * bv.y; acc[3][2] += a3 * bv.z; acc[3][3] += a3 * bv.w;
        }
#pragma unroll
        for (int ii = 0; ii < 4; ii++) {
            float4 v = {acc[ii][0], acc[ii][1], acc[ii][2], acc[ii][3]};
            *(float4*)(comp + (size_t)(row0 + i0 + ii) * DIM + d0) = v;
        }
    }
}

// ---------------- launch ----------------
extern "C" void kernel_launch(void* const* d_in, const int* in_sizes, int n_in,
                              void* d_out, int out_size) {
    const float* W  = (const float*)d_in[0];
    const float* C0 = (const float*)d_in[1];
    float* out  = (float*)d_out;
    float* comp = out;                                    // [N, D]
    float* clus = out + (size_t)NROWS * DIM;              // [K, D]
    float* attn = clus + (size_t)KC * DIM;                // [N, K]

    int sms = 0;
    cudaDeviceGetAttribute(&sms, cudaDevAttrMultiProcessorCount, 0);
    if (sms <= 0 || sms > MAXGRID) sms = MAXGRID;

    const int smem_iter  = 31680 * (int)sizeof(float);    // 126720 B -> occ 1, all resident
    const int smem_final = 17280 * (int)sizeof(float);    // 69120 B
    cudaFuncSetAttribute(iter_fused, cudaFuncAttributeMaxDynamicSharedMemorySize, smem_iter);
    cudaFuncSetAttribute(final_fused, cudaFuncAttributeMaxDynamicSharedMemorySize, smem_final);

    init_kernel<<<NROWS / TPB, TPB>>>(W, C0);
    for (int it = 0; it < ITERS; it++)
        iter_fused<<<sms, TPB, smem_iter>>>(it, W);
    final_fused<<<NROWS / 64, TPB, smem_final>>>(W, attn, comp, clus);
}

// round 7
// speedup vs baseline: 2.1383x; 1.0346x over previous
#include <cuda_runtime.h>
#include <math.h>
#include <stdint.h>

#define NROWS 131072
#define DIM 64
#define KC 64
#define ITERS 10
#define TPB 256
#define MT 128                    // rows per tile
#define NT (NROWS / MT)           // 1024 tiles
#define MAXGRID 148
#define PSTR (64 * 68)            // floats per partial slot

// ---------------- device globals (no cudaMalloc allowed) ----------------
__device__ float g_clusters[KC * DIM];
__device__ float g_prev[KC * DIM];          // clusters used by last active iteration
__device__ float g_part[(size_t)(4 * MAXGRID) * PSTR];   // up to 592 slots
__device__ float g_normk[KC];
__device__ float g_wsq[NROWS];
__device__ int   g_done;
__device__ volatile int g_sync[2];

// ---------------- helpers ----------------
__device__ __forceinline__ uint32_t f2t(float x) {
    uint32_t u;
    asm("cvt.rna.tf32.f32 %0, %1;" : "=r"(u) : "f"(x));
    return u;
}
__device__ __forceinline__ void mma8(float c[4], uint32_t a0, uint32_t a1, uint32_t a2,
                                     uint32_t a3, uint32_t b0, uint32_t b1) {
    asm volatile(
        "mma.sync.aligned.m16n8k8.row.col.f32.tf32.tf32.f32 "
        "{%0,%1,%2,%3},{%4,%5,%6,%7},{%8,%9},{%0,%1,%2,%3};"
        : "+f"(c[0]), "+f"(c[1]), "+f"(c[2]), "+f"(c[3])
        : "r"(a0), "r"(a1), "r"(a2), "r"(a3), "r"(b0), "r"(b1));
}
#define BITS(x) (__float_as_uint(x))

// deterministic grid-wide sync: monotonic counters, per-launch target
__device__ __forceinline__ void gsync(int j, int target) {
    __syncthreads();
    if (threadIdx.x == 0) {
        __threadfence();
        atomicAdd((int*)&g_sync[j], 1);
        while (g_sync[j] < target) { }
        __threadfence();
    }
    __syncthreads();
}

// ---------------- init: flags, counters, cluster copy, ||w||^2 ----------------
__global__ void init_kernel(const float* __restrict__ W, const float* __restrict__ C0) {
    int gid = blockIdx.x * blockDim.x + threadIdx.x;   // NROWS threads
    if (gid == 0) { g_done = 0; g_sync[0] = 0; g_sync[1] = 0; }
    if (gid < KC * DIM) g_clusters[gid] = C0[gid];
    const float4* p = (const float4*)(W + (size_t)gid * DIM);
    float s = 0.f;
#pragma unroll
    for (int j = 0; j < 16; j++) {
        float4 v = p[j];
        s += v.x * v.x + v.y * v.y + v.z * v.z + v.w * v.w;
    }
    g_wsq[gid] = s;
}

// ---------------- fully fused iteration kernel (occ 2, 296 blocks) ----------------
__global__ __launch_bounds__(TPB, 2) void iter_fused(int it, const float* __restrict__ W) {
    if (g_done) return;
    extern __shared__ float sm[];
    float* cl   = sm;          // [64][68] clusters (tf32-rounded)
    float* csq  = sm + 4352;   // [64] exact ||c||^2
    float* w    = sm + 4416;   // [128][72] W tile (tf32); col64=1, cols65-71=0
    float* att  = sm + 13632;  // [128][72] attn tile (tf32)
    float* wsqs = sm + 22848;  // [128]

    const int tid = threadIdx.x;
    const int lane = tid & 31, wid = tid >> 5;
    const int gid = lane >> 2, tig = lane & 3;
    const int m1 = wid * 16;            // GEMM1 row offset
    const int m2 = (wid & 3) * 16;      // GEMM2 kc offset
    const int rh = (wid >> 2) * 64;     // GEMM2 row-half offset
    const int target = (it + 1) * (int)gridDim.x;

    for (int i = tid; i < KC * DIM; i += TPB)
        cl[(i >> 6) * 68 + (i & 63)] = __uint_as_float(f2t(g_clusters[i]));
    if (tid < KC) {
        float s = 0.f;
#pragma unroll
        for (int d = 0; d < DIM; d++) { float v = g_clusters[tid * DIM + d]; s += v * v; }
        csq[tid] = s;
    }
    // persistent ones/zeros in cols 64..71 of w (colsum trick needs finite values)
    for (int i = tid; i < MT * 8; i += TPB) {
        int r = i >> 3, c = i & 7;
        w[r * 72 + 64 + c] = (c == 0) ? 1.0f : 0.0f;
    }

    float c2[9][4];
#pragma unroll
    for (int j = 0; j < 9; j++) { c2[j][0] = c2[j][1] = c2[j][2] = c2[j][3] = 0.f; }

    for (int tile = blockIdx.x; tile < NT; tile += gridDim.x) {
        const size_t row0 = (size_t)tile * MT;
        __syncthreads();
        for (int i = tid * 4; i < MT * DIM; i += TPB * 4) {
            float4 v = *(const float4*)(W + row0 * DIM + i);
            v.x = __uint_as_float(f2t(v.x));
            v.y = __uint_as_float(f2t(v.y));
            v.z = __uint_as_float(f2t(v.z));
            v.w = __uint_as_float(f2t(v.w));
            *(float4*)(w + (i >> 6) * 72 + (i & 63)) = v;
        }
        if (tid < MT) wsqs[tid] = g_wsq[row0 + tid];
        __syncthreads();

        // ---- GEMM1: C1[row][kc] = W * C^T ----
        float c1[8][4];
#pragma unroll
        for (int j = 0; j < 8; j++) { c1[j][0] = c1[j][1] = c1[j][2] = c1[j][3] = 0.f; }
        const float* Ab = w + (m1 + gid) * 72 + tig;
#pragma unroll 4
        for (int s = 0; s < 8; s++) {
            const int k0 = 8 * s;
            uint32_t a0 = BITS(Ab[k0]);
            uint32_t a1 = BITS(Ab[8 * 72 + k0]);
            uint32_t a2 = BITS(Ab[k0 + 4]);
            uint32_t a3 = BITS(Ab[8 * 72 + k0 + 4]);
            const float* Bb = cl + gid * 68 + k0 + tig;
#pragma unroll
            for (int j = 0; j < 8; j++) {
                uint32_t b0 = BITS(Bb[j * 544]);
                uint32_t b1 = BITS(Bb[j * 544 + 4]);
                mma8(c1[j], a0, a1, a2, a3, b0, b1);
            }
        }

        // ---- softmax row A (m1+gid), then row B (m1+gid+8); one e[16] live at a time ----
        {
            float ws = wsqs[m1 + gid];
            float e[16], mn = 3.4e38f;
#pragma unroll
            for (int j = 0; j < 8; j++) {
                float2 cq = *(const float2*)(csq + 8 * j + 2 * tig);
                float d0 = sqrtf(fmaxf(ws + cq.x - 2.f * c1[j][0], 0.f));
                float d1 = sqrtf(fmaxf(ws + cq.y - 2.f * c1[j][1], 0.f));
                e[2 * j] = d0; e[2 * j + 1] = d1;
                mn = fminf(mn, fminf(d0, d1));
            }
            mn = fminf(mn, __shfl_xor_sync(0xffffffffu, mn, 1));
            mn = fminf(mn, __shfl_xor_sync(0xffffffffu, mn, 2));
            float s = 0.f;
#pragma unroll
            for (int j = 0; j < 16; j++) { e[j] = __expf(mn - e[j]); s += e[j]; }
            s += __shfl_xor_sync(0xffffffffu, s, 1);
            s += __shfl_xor_sync(0xffffffffu, s, 2);
            float inv = 1.f / s;
            float* wA = att + (m1 + gid) * 72 + 2 * tig;
#pragma unroll
            for (int j = 0; j < 8; j++) {
                float2 v = make_float2(__uint_as_float(f2t(e[2 * j] * inv)),
                                       __uint_as_float(f2t(e[2 * j + 1] * inv)));
                *(float2*)(wA + 8 * j) = v;
            }
        }
        {
            float ws = wsqs[m1 + gid + 8];
            float e[16], mn = 3.4e38f;
#pragma unroll
            for (int j = 0; j < 8; j++) {
                float2 cq = *(const float2*)(csq + 8 * j + 2 * tig);
                float d0 = sqrtf(fmaxf(ws + cq.x - 2.f * c1[j][2], 0.f));
                float d1 = sqrtf(fmaxf(ws + cq.y - 2.f * c1[j][3], 0.f));
                e[2 * j] = d0; e[2 * j + 1] = d1;
                mn = fminf(mn, fminf(d0, d1));
            }
            mn = fminf(mn, __shfl_xor_sync(0xffffffffu, mn, 1));
            mn = fminf(mn, __shfl_xor_sync(0xffffffffu, mn, 2));
            float s = 0.f;
#pragma unroll
            for (int j = 0; j < 16; j++) { e[j] = __expf(mn - e[j]); s += e[j]; }
            s += __shfl_xor_sync(0xffffffffu, s, 1);
            s += __shfl_xor_sync(0xffffffffu, s, 2);
            float inv = 1.f / s;
            float* wB = att + (m1 + gid + 8) * 72 + 2 * tig;
#pragma unroll
            for (int j = 0; j < 8; j++) {
                float2 v = make_float2(__uint_as_float(f2t(e[2 * j] * inv)),
                                       __uint_as_float(f2t(e[2 * j + 1] * inv)));
                *(float2*)(wB + 8 * j) = v;
            }
        }
        __syncthreads();

        // ---- GEMM2: C2[kc][d] += attn^T * W  (9th n-frag vs ones col = colsum) ----
        const float* A2 = att + (rh + tig) * 72 + m2 + gid;
        const float* B2 = w + (rh + tig) * 72 + gid;
#pragma unroll 4
        for (int s = 0; s < 8; s++) {
            const int o = s * 8 * 72;
            uint32_t a0 = BITS(A2[o]);
            uint32_t a1 = BITS(A2[o + 8]);
            uint32_t a2 = BITS(A2[o + 4 * 72]);
            uint32_t a3 = BITS(A2[o + 4 * 72 + 8]);
#pragma unroll
            for (int j = 0; j < 9; j++) {
                uint32_t b0 = BITS(B2[o + 8 * j]);
                uint32_t b1 = BITS(B2[o + 4 * 72 + 8 * j]);
                mma8(c2[j], a0, a1, a2, a3, b0, b1);
            }
        }
    }

    // ---- per-(block, row-half) partials ----
    {
        float* P = g_part + (size_t)(blockIdx.x * 2 + (wid >> 2)) * PSTR;
#pragma unroll
        for (int j = 0; j < 8; j++) {
            *(float2*)(P + (m2 + gid) * 68 + 8 * j + 2 * tig) = make_float2(c2[j][0], c2[j][1]);
            *(float2*)(P + (m2 + gid + 8) * 68 + 8 * j + 2 * tig) = make_float2(c2[j][2], c2[j][3]);
        }
        if (tig == 0) {
            P[(m2 + gid) * 68 + 64] = c2[8][0];
            P[(m2 + gid + 8) * 68 + 64] = c2[8][2];
        }
    }

    gsync(0, target);

    // ---- blocks 0..63 reduce partials for their k ----
    float nv = 0.f, ov = 0.f;
    const int kblk = blockIdx.x;
    if (kblk < 64) {
        float* r_num = sm;          // [4][64]
        float* r_den = sm + 256;    // [4]
        float* s_nrm = sm + 264;    // [2]
        const int q = tid >> 6, d = tid & 63;
        const int nslots = (int)gridDim.x * 2;
        float s = 0.f, sden = 0.f;
        const float* base = g_part + kblk * 68;
        for (int b = q; b < nslots; b += 4) {
            const float* P = base + (size_t)b * PSTR;
            s += P[d];
            if (d == 0) sden += P[64];
        }
        r_num[q * 64 + d] = s;
        if (d == 0) r_den[q] = sden;
        __syncthreads();
        if (tid < 64) {
            float num = (r_num[tid] + r_num[64 + tid]) + (r_num[128 + tid] + r_num[192 + tid]);
            float den = (r_den[0] + r_den[1]) + (r_den[2] + r_den[3]);
            nv = num / den;
            ov = g_clusters[kblk * 64 + tid];
            float x = (nv - ov) * (nv - ov);
#pragma unroll
            for (int o = 16; o > 0; o >>= 1) x += __shfl_xor_sync(0xffffffffu, x, o);
            if ((tid & 31) == 0) s_nrm[tid >> 5] = x;
        }
        __syncthreads();
        if (tid == 0) g_normk[kblk] = s_nrm[0] + s_nrm[1];
    }

    gsync(1, target);

    // ---- convergence decision (redundant per block) + commit ----
    if (kblk < 64) {
        __shared__ int s_conv;
        if (tid == 0) {
            float t = 0.f;
            for (int k = 0; k < 64; k++) t += g_normk[k];
            int conv = (sqrtf(t) <= 1e-4f) ? 1 : 0;
            s_conv = conv;
            if (kblk == 0 && conv) g_done = 1;   // freeze for remaining launches
        }
        __syncthreads();
        if (tid < 64) {
            g_prev[kblk * 64 + tid] = ov;
            g_clusters[kblk * 64 + tid] = s_conv ? ov : nv;
        }
    }
}

// ---------------- fused final: attn (tf32 GEMM1 + fp32 softmax) + compressed + clusters ----------------
__global__ __launch_bounds__(TPB, 2) void final_fused(const float* __restrict__ W,
                                                      float* __restrict__ attn_out,
                                                      float* __restrict__ comp,
                                                      float* __restrict__ clus_out) {
    extern __shared__ float sm[];
    float* cl  = sm;          // [64][68] tf32(g_prev)
    float* csq = sm + 4352;   // [64] exact ||c_prev||^2
    float* w   = sm + 4416;   // [128][72] tf32 W tile
    float* att = sm + 13632;  // [128][72] fp32 attn
    float* cs  = sm + 22848;  // [64][64] fp32 g_clusters
    float* wsq = sm + 26944;  // [128]

    const int tid = threadIdx.x;
    const int lane = tid & 31, wid = tid >> 5;
    const int gid = lane >> 2, tig = lane & 3;
    const int m1 = wid * 16;
    const size_t row0 = (size_t)blockIdx.x * MT;

    for (int i = tid; i < KC * DIM; i += TPB) {
        cl[(i >> 6) * 68 + (i & 63)] = __uint_as_float(f2t(g_prev[i]));
        float cv = g_clusters[i];
        cs[i] = cv;
        if (blockIdx.x == 0) clus_out[i] = cv;
    }
    if (tid < KC) {
        float s = 0.f;
#pragma unroll
        for (int d = 0; d < DIM; d++) { float v = g_prev[tid * DIM + d]; s += v * v; }
        csq[tid] = s;
    }
    for (int i = tid * 4; i < MT * DIM; i += TPB * 4) {
        float4 v = *(const float4*)(W + row0 * DIM + i);
        v.x = __uint_as_float(f2t(v.x));
        v.y = __uint_as_float(f2t(v.y));
        v.z = __uint_as_float(f2t(v.z));
        v.w = __uint_as_float(f2t(v.w));
        *(float4*)(w + (i >> 6) * 72 + (i & 63)) = v;
    }
    if (tid < MT) wsq[tid] = g_wsq[row0 + tid];
    __syncthreads();

    // ---- GEMM1 (tf32 mma): C1[row][kc] = W * C_prev^T ----
    float c1[8][4];
#pragma unroll
    for (int j = 0; j < 8; j++) { c1[j][0] = c1[j][1] = c1[j][2] = c1[j][3] = 0.f; }
    const float* Ab = w + (m1 + gid) * 72 + tig;
#pragma unroll 4
    for (int s = 0; s < 8; s++) {
        const int k0 = 8 * s;
        uint32_t a0 = BITS(Ab[k0]);
        uint32_t a1 = BITS(Ab[8 * 72 + k0]);
        uint32_t a2 = BITS(Ab[k0 + 4]);
        uint32_t a3 = BITS(Ab[8 * 72 + k0 + 4]);
        const float* Bb = cl + gid * 68 + k0 + tig;
#pragma unroll
        for (int j = 0; j < 8; j++) {
            uint32_t b0 = BITS(Bb[j * 544]);
            uint32_t b1 = BITS(Bb[j * 544 + 4]);
            mma8(c1[j], a0, a1, a2, a3, b0, b1);
        }
    }

    // ---- softmax rows (fp32 attn into smem) ----
    {
        float ws = wsq[m1 + gid];
        float e[16], mn = 3.4e38f;
#pragma unroll
        for (int j = 0; j < 8; j++) {
            float2 cq = *(const float2*)(csq + 8 * j + 2 * tig);
            float d0 = sqrtf(fmaxf(ws + cq.x - 2.f * c1[j][0], 0.f));
            float d1 = sqrtf(fmaxf(ws + cq.y - 2.f * c1[j][1], 0.f));
            e[2 * j] = d0; e[2 * j + 1] = d1;
            mn = fminf(mn, fminf(d0, d1));
        }
        mn = fminf(mn, __shfl_xor_sync(0xffffffffu, mn, 1));
        mn = fminf(mn, __shfl_xor_sync(0xffffffffu, mn, 2));
        float s = 0.f;
#pragma unroll
        for (int j = 0; j < 16; j++) { e[j] = __expf(mn - e[j]); s += e[j]; }
        s += __shfl_xor_sync(0xffffffffu, s, 1);
        s += __shfl_xor_sync(0xffffffffu, s, 2);
        float inv = 1.f / s;
        float* wA = att + (m1 + gid) * 72 + 2 * tig;
#pragma unroll
        for (int j = 0; j < 8; j++)
            *(float2*)(wA + 8 * j) = make_float2(e[2 * j] * inv, e[2 * j + 1] * inv);
    }
    {
        float ws = wsq[m1 + gid + 8];
        float e[16], mn = 3.4e38f;
#pragma unroll
        for (int j = 0; j < 8; j++) {
            float2 cq = *(const float2*)(csq + 8 * j + 2 * tig);
            float d0 = sqrtf(fmaxf(ws + cq.x - 2.f * c1[j][2], 0.f));
            float d1 = sqrtf(fmaxf(ws + cq.y - 2.f * c1[j][3], 0.f));
            e[2 * j] = d0; e[2 * j + 1] = d1;
            mn = fminf(mn, fminf(d0, d1));
        }
        mn = fminf(mn, __shfl_xor_sync(0xffffffffu, mn, 1));
        mn = fminf(mn, __shfl_xor_sync(0xffffffffu, mn, 2));
        float s = 0.f;
#pragma unroll
        for (int j = 0; j < 16; j++) { e[j] = __expf(mn - e[j]); s += e[j]; }
        s += __shfl_xor_sync(0xffffffffu, s, 1);
        s += __shfl_xor_sync(0xffffffffu, s, 2);
        float inv = 1.f / s;
        float* wB = att + (m1 + gid + 8) * 72 + 2 * tig;
#pragma unroll
        for (int j = 0; j < 8; j++)
            *(float2*)(wB + 8 * j) = make_float2(e[2 * j] * inv, e[2 * j + 1] * inv);
    }
    __syncthreads();

    // ---- coalesced attn writeback ----
    for (int i = tid * 4; i < MT * KC; i += TPB * 4) {
        int r = i >> 6, c = i & 63;
        float4 v = *(float4*)(att + r * 72 + c);
        *(float4*)(attn_out + (row0 + r) * KC + c) = v;
    }

    // ---- GEMM3 (fp32 FFMA): comp = attn @ clusters ----
    {
        const int ty = tid >> 4, tx = tid & 15;
        const int i0 = ty * 8, d0 = tx * 4;
        float acc[8][4];
#pragma unroll
        for (int a = 0; a < 8; a++)
#pragma unroll
            for (int b = 0; b < 4; b++) acc[a][b] = 0.f;
#pragma unroll 4
        for (int k = 0; k < KC; k++) {
            float4 bv = *(float4*)(cs + k * 64 + d0);
#pragma unroll
            for (int ii = 0; ii < 8; ii++) {
                float a = att[(i0 + ii) * 72 + k];
                acc[ii][0] += a * bv.x;
                acc[ii][1] += a * bv.y;
                acc[ii][2] += a * bv.z;
                acc[ii][3] += a * bv.w;
            }
        }
#pragma unroll
        for (int ii = 0; ii < 8; ii++) {
            float4 v = {acc[ii][0], acc[ii][1], acc[ii][2], acc[ii][3]};
            *(float4*)(comp + (row0 + i0 + ii) * DIM + d0) = v;
        }
    }
}

// ---------------- launch ----------------
extern "C" void kernel_launch(void* const* d_in, const int* in_sizes, int n_in,
                              void* d_out, int out_size) {
    const float* W  = (const float*)d_in[0];
    const float* C0 = (const float*)d_in[1];
    float* out  = (float*)d_out;
    float* comp = out;                                    // [N, D]
    float* clus = out + (size_t)NROWS * DIM;              // [K, D]
    float* attn = clus + (size_t)KC * DIM;                // [N, K]

    int sms = 0;
    cudaDeviceGetAttribute(&sms, cudaDevAttrMultiProcessorCount, 0);
    if (sms <= 0 || sms > MAXGRID) sms = MAXGRID;
    const int grid_iter = 2 * sms;                        // 2 CTAs/SM, all resident

    const int smem_iter  = 22976 * (int)sizeof(float);    // 91904 B  -> occ 2
    const int smem_final = 27072 * (int)sizeof(float);    // 108288 B -> occ 2
    cudaFuncSetAttribute(iter_fused, cudaFuncAttributeMaxDynamicSharedMemorySize, smem_iter);
    cudaFuncSetAttribute(final_fused, cudaFuncAttributeMaxDynamicSharedMemorySize, smem_final);

    init_kernel<<<NROWS / TPB, TPB>>>(W, C0);
    for (int it = 0; it < ITERS; it++)
        iter_fused<<<grid_iter, TPB, smem_iter>>>(it, W);
    final_fused<<<NROWS / MT, TPB, smem_final>>>(W, attn, comp, clus);
}

// round 8
// speedup vs baseline: 2.4212x; 1.1323x over previous
#include <cuda_runtime.h>
#include <math.h>
#include <stdint.h>

#define NROWS 131072
#define DIM 64
#define KC 64
#define ITERS 10
#define TPB 256
#define MT 128                    // rows per tile
#define NT (NROWS / MT)           // 1024 tiles
#define MAXGRID 148
#define PSTR (64 * 68)            // floats per partial slot

// ---------------- device globals (no cudaMalloc allowed) ----------------
__device__ float g_clusters[KC * DIM];
__device__ float g_prev[KC * DIM];          // clusters used by last active iteration
__device__ float g_part[(size_t)(2 * MAXGRID) * PSTR];   // 1 slot per block
__device__ float g_normk[KC];
__device__ float g_wsq[NROWS];
__device__ int   g_done;
__device__ volatile int g_sync[2];

// ---------------- helpers ----------------
__device__ __forceinline__ uint32_t f2t(float x) {
    uint32_t u;
    asm("cvt.rna.tf32.f32 %0, %1;" : "=r"(u) : "f"(x));
    return u;
}
__device__ __forceinline__ float fsqrt_fast(float x) {
    float r;
    asm("sqrt.approx.f32 %0, %1;" : "=f"(r) : "f"(x));
    return r;
}
__device__ __forceinline__ void mma8(float c[4], uint32_t a0, uint32_t a1, uint32_t a2,
                                     uint32_t a3, uint32_t b0, uint32_t b1) {
    asm("mma.sync.aligned.m16n8k8.row.col.f32.tf32.tf32.f32 "
        "{%0,%1,%2,%3},{%4,%5,%6,%7},{%8,%9},{%0,%1,%2,%3};"
        : "+f"(c[0]), "+f"(c[1]), "+f"(c[2]), "+f"(c[3])
        : "r"(a0), "r"(a1), "r"(a2), "r"(a3), "r"(b0), "r"(b1));
}
#define BITS(x) (__float_as_uint(x))

// deterministic grid-wide sync: monotonic counters, per-launch target
__device__ __forceinline__ void gsync(int j, int target) {
    __syncthreads();
    if (threadIdx.x == 0) {
        __threadfence();
        atomicAdd((int*)&g_sync[j], 1);
        while (g_sync[j] < target) { }
        __threadfence();
    }
    __syncthreads();
}

// ---------------- init: flags, counters, cluster copy, ||w||^2 ----------------
__global__ void init_kernel(const float* __restrict__ W, const float* __restrict__ C0) {
    int gid = blockIdx.x * blockDim.x + threadIdx.x;   // NROWS threads
    if (gid == 0) { g_done = 0; g_sync[0] = 0; g_sync[1] = 0; }
    if (gid < KC * DIM) g_clusters[gid] = C0[gid];
    const float4* p = (const float4*)(W + (size_t)gid * DIM);
    float s = 0.f;
#pragma unroll
    for (int j = 0; j < 16; j++) {
        float4 v = p[j];
        s += v.x * v.x + v.y * v.y + v.z * v.z + v.w * v.w;
    }
    g_wsq[gid] = s;
}

// ---------------- fully fused iteration kernel (occ 2, 296 blocks) ----------------
__global__ __launch_bounds__(TPB, 2) void iter_fused(int it, const float* __restrict__ W) {
    if (g_done) return;
    extern __shared__ float sm[];
    float* cl   = sm;          // [64][68] clusters (tf32-rounded)
    float* csq  = sm + 4352;   // [64] exact ||c||^2
    float* w    = sm + 4416;   // [128][72] W tile (tf32); col64=1, cols65-71=0
    float* att  = sm + 13632;  // [128][72] attn tile (tf32); reused as c2 stage at end
    float* wsqs = sm + 22848;  // [128]

    const int tid = threadIdx.x;
    const int lane = tid & 31, wid = tid >> 5;
    const int gid = lane >> 2, tig = lane & 3;
    const int m1 = wid * 16;            // GEMM1 row offset
    const int m2 = (wid & 3) * 16;      // GEMM2 kc offset
    const int rh = (wid >> 2) * 64;     // GEMM2 row-half offset
    const int target = (it + 1) * (int)gridDim.x;

    for (int i = tid; i < KC * DIM; i += TPB)
        cl[(i >> 6) * 68 + (i & 63)] = __uint_as_float(f2t(g_clusters[i]));
    if (tid < KC) {
        float s = 0.f;
#pragma unroll
        for (int d = 0; d < DIM; d++) { float v = g_clusters[tid * DIM + d]; s += v * v; }
        csq[tid] = s;
    }
    // persistent ones/zeros in cols 64..71 of w (colsum trick)
    for (int i = tid; i < MT * 8; i += TPB) {
        int r = i >> 3, c = i & 7;
        w[r * 72 + 64 + c] = (c == 0) ? 1.0f : 0.0f;
    }

    float c2[9][4];
#pragma unroll
    for (int j = 0; j < 9; j++) { c2[j][0] = c2[j][1] = c2[j][2] = c2[j][3] = 0.f; }

    // ---- prefetch first tile into registers ----
    float4 rw[8];
    float wsq_pf = 0.f;
    {
        const float* src = W + (size_t)blockIdx.x * MT * DIM;
#pragma unroll
        for (int j = 0; j < 8; j++) rw[j] = *(const float4*)(src + tid * 4 + j * 1024);
        if (tid < MT) wsq_pf = g_wsq[(size_t)blockIdx.x * MT + tid];
    }

    for (int tile = blockIdx.x; tile < NT; tile += gridDim.x) {
        __syncthreads();   // w/att free (previous GEMM2 done; init done on first pass)
        // store prefetched tile (tf32-rounded) into smem
#pragma unroll
        for (int j = 0; j < 8; j++) {
            const int i = tid * 4 + j * 1024;
            float4 v = rw[j];
            v.x = __uint_as_float(f2t(v.x));
            v.y = __uint_as_float(f2t(v.y));
            v.z = __uint_as_float(f2t(v.z));
            v.w = __uint_as_float(f2t(v.w));
            *(float4*)(w + (i >> 6) * 72 + (i & 63)) = v;
        }
        if (tid < MT) wsqs[tid] = wsq_pf;
        __syncthreads();

        // issue prefetch for next tile (retires under GEMM1+softmax)
        const int nt = tile + (int)gridDim.x;
        if (nt < NT) {
            const float* src = W + (size_t)nt * MT * DIM;
#pragma unroll
            for (int j = 0; j < 8; j++) rw[j] = *(const float4*)(src + tid * 4 + j * 1024);
            if (tid < MT) wsq_pf = g_wsq[(size_t)nt * MT + tid];
        }

        // ---- GEMM1: C1[row][kc] = W * C^T ----
        float c1[8][4];
#pragma unroll
        for (int j = 0; j < 8; j++) { c1[j][0] = c1[j][1] = c1[j][2] = c1[j][3] = 0.f; }
        const float* Ab = w + (m1 + gid) * 72 + tig;
#pragma unroll 4
        for (int s = 0; s < 8; s++) {
            const int k0 = 8 * s;
            uint32_t a0 = BITS(Ab[k0]);
            uint32_t a1 = BITS(Ab[8 * 72 + k0]);
            uint32_t a2 = BITS(Ab[k0 + 4]);
            uint32_t a3 = BITS(Ab[8 * 72 + k0 + 4]);
            const float* Bb = cl + gid * 68 + k0 + tig;
#pragma unroll
            for (int j = 0; j < 8; j++) {
                uint32_t b0 = BITS(Bb[j * 544]);
                uint32_t b1 = BITS(Bb[j * 544 + 4]);
                mma8(c1[j], a0, a1, a2, a3, b0, b1);
            }
        }

        // ---- softmax row A (m1+gid), then row B (m1+gid+8) ----
        {
            float ws = wsqs[m1 + gid];
            float e[16], mn = 3.4e38f;
#pragma unroll
            for (int j = 0; j < 8; j++) {
                float2 cq = *(const float2*)(csq + 8 * j + 2 * tig);
                float d0 = fsqrt_fast(fmaxf(ws + cq.x - 2.f * c1[j][0], 0.f));
                float d1 = fsqrt_fast(fmaxf(ws + cq.y - 2.f * c1[j][1], 0.f));
                e[2 * j] = d0; e[2 * j + 1] = d1;
                mn = fminf(mn, fminf(d0, d1));
            }
            mn = fminf(mn, __shfl_xor_sync(0xffffffffu, mn, 1));
            mn = fminf(mn, __shfl_xor_sync(0xffffffffu, mn, 2));
            float s = 0.f;
#pragma unroll
            for (int j = 0; j < 16; j++) { e[j] = __expf(mn - e[j]); s += e[j]; }
            s += __shfl_xor_sync(0xffffffffu, s, 1);
            s += __shfl_xor_sync(0xffffffffu, s, 2);
            float inv = 1.f / s;
            float* wA = att + (m1 + gid) * 72 + 2 * tig;
#pragma unroll
            for (int j = 0; j < 8; j++) {
                float2 v = make_float2(__uint_as_float(f2t(e[2 * j] * inv)),
                                       __uint_as_float(f2t(e[2 * j + 1] * inv)));
                *(float2*)(wA + 8 * j) = v;
            }
        }
        {
            float ws = wsqs[m1 + gid + 8];
            float e[16], mn = 3.4e38f;
#pragma unroll
            for (int j = 0; j < 8; j++) {
                float2 cq = *(const float2*)(csq + 8 * j + 2 * tig);
                float d0 = fsqrt_fast(fmaxf(ws + cq.x - 2.f * c1[j][2], 0.f));
                float d1 = fsqrt_fast(fmaxf(ws + cq.y - 2.f * c1[j][3], 0.f));
                e[2 * j] = d0; e[2 * j + 1] = d1;
                mn = fminf(mn, fminf(d0, d1));
            }
            mn = fminf(mn, __shfl_xor_sync(0xffffffffu, mn, 1));
            mn = fminf(mn, __shfl_xor_sync(0xffffffffu, mn, 2));
            float s = 0.f;
#pragma unroll
            for (int j = 0; j < 16; j++) { e[j] = __expf(mn - e[j]); s += e[j]; }
            s += __shfl_xor_sync(0xffffffffu, s, 1);
            s += __shfl_xor_sync(0xffffffffu, s, 2);
            float inv = 1.f / s;
            float* wB = att + (m1 + gid + 8) * 72 + 2 * tig;
#pragma unroll
            for (int j = 0; j < 8; j++) {
                float2 v = make_float2(__uint_as_float(f2t(e[2 * j] * inv)),
                                       __uint_as_float(f2t(e[2 * j + 1] * inv)));
                *(float2*)(wB + 8 * j) = v;
            }
        }
        __syncthreads();

        // ---- GEMM2: C2[kc][d] += attn^T * W  (9th n-frag vs ones col = colsum) ----
        const float* A2 = att + (rh + tig) * 72 + m2 + gid;
        const float* B2 = w + (rh + tig) * 72 + gid;
#pragma unroll 4
        for (int s = 0; s < 8; s++) {
            const int o = s * 8 * 72;
            uint32_t a0 = BITS(A2[o]);
            uint32_t a1 = BITS(A2[o + 8]);
            uint32_t a2 = BITS(A2[o + 4 * 72]);
            uint32_t a3 = BITS(A2[o + 4 * 72 + 8]);
#pragma unroll
            for (int j = 0; j < 9; j++) {
                uint32_t b0 = BITS(B2[o + 8 * j]);
                uint32_t b1 = BITS(B2[o + 4 * 72 + 8 * j]);
                mma8(c2[j], a0, a1, a2, a3, b0, b1);
            }
        }
    }

    // ---- combine row-halves in smem, write ONE partial slot per block ----
    __syncthreads();                    // everyone done reading att/w
    {
        float* stage = att;             // [64][72] c2 of row-half 1
        if (rh) {
#pragma unroll
            for (int j = 0; j < 8; j++) {
                *(float2*)(stage + (m2 + gid) * 72 + 8 * j + 2 * tig) = make_float2(c2[j][0], c2[j][1]);
                *(float2*)(stage + (m2 + gid + 8) * 72 + 8 * j + 2 * tig) = make_float2(c2[j][2], c2[j][3]);
            }
            if (tig == 0) {
                stage[(m2 + gid) * 72 + 64] = c2[8][0];
                stage[(m2 + gid + 8) * 72 + 64] = c2[8][2];
            }
        }
        __syncthreads();
        if (!rh) {
            float* P = g_part + (size_t)blockIdx.x * PSTR;
#pragma unroll
            for (int j = 0; j < 8; j++) {
                float2 s0 = *(float2*)(stage + (m2 + gid) * 72 + 8 * j + 2 * tig);
                float2 s1 = *(float2*)(stage + (m2 + gid + 8) * 72 + 8 * j + 2 * tig);
                *(float2*)(P + (m2 + gid) * 68 + 8 * j + 2 * tig) =
                    make_float2(c2[j][0] + s0.x, c2[j][1] + s0.y);
                *(float2*)(P + (m2 + gid + 8) * 68 + 8 * j + 2 * tig) =
                    make_float2(c2[j][2] + s1.x, c2[j][3] + s1.y);
            }
            if (tig == 0) {
                P[(m2 + gid) * 68 + 64] = c2[8][0] + stage[(m2 + gid) * 72 + 64];
                P[(m2 + gid + 8) * 68 + 64] = c2[8][2] + stage[(m2 + gid + 8) * 72 + 64];
            }
        }
    }

    gsync(0, target);

    // ---- blocks 0..63 reduce partials for their k ----
    float nv = 0.f, ov = 0.f;
    const int kblk = blockIdx.x;
    if (kblk < 64) {
        float* r_num = sm;          // [4][64]
        float* r_den = sm + 256;    // [4]
        float* s_nrm = sm + 264;    // [2]
        const int q = tid >> 6, d = tid & 63;
        const int nslots = (int)gridDim.x;
        float s = 0.f, sden = 0.f;
        const float* base = g_part + kblk * 68;
        for (int b = q; b < nslots; b += 4) {
            const float* P = base + (size_t)b * PSTR;
            s += P[d];
            if (d == 0) sden += P[64];
        }
        r_num[q * 64 + d] = s;
        if (d == 0) r_den[q] = sden;
        __syncthreads();
        if (tid < 64) {
            float num = (r_num[tid] + r_num[64 + tid]) + (r_num[128 + tid] + r_num[192 + tid]);
            float den = (r_den[0] + r_den[1]) + (r_den[2] + r_den[3]);
            nv = num / den;
            ov = g_clusters[kblk * 64 + tid];
            float x = (nv - ov) * (nv - ov);
#pragma unroll
            for (int o = 16; o > 0; o >>= 1) x += __shfl_xor_sync(0xffffffffu, x, o);
            if ((tid & 31) == 0) s_nrm[tid >> 5] = x;
        }
        __syncthreads();
        if (tid == 0) g_normk[kblk] = s_nrm[0] + s_nrm[1];
    }

    gsync(1, target);

    // ---- convergence decision (redundant per block) + commit ----
    if (kblk < 64) {
        __shared__ int s_conv;
        if (tid == 0) {
            float t = 0.f;
            for (int k = 0; k < 64; k++) t += g_normk[k];
            int conv = (sqrtf(t) <= 1e-4f) ? 1 : 0;
            s_conv = conv;
            if (kblk == 0 && conv) g_done = 1;   // freeze for remaining launches
        }
        __syncthreads();
        if (tid < 64) {
            g_prev[kblk * 64 + tid] = ov;
            g_clusters[kblk * 64 + tid] = s_conv ? ov : nv;
        }
    }
}

// ---------------- fused final: attn (tf32 GEMM1 + fp32 softmax) + compressed + clusters ----------------
__global__ __launch_bounds__(TPB, 2) void final_fused(const float* __restrict__ W,
                                                      float* __restrict__ attn_out,
                                                      float* __restrict__ comp,
                                                      float* __restrict__ clus_out) {
    extern __shared__ float sm[];
    float* cl  = sm;          // [64][68] tf32(g_prev)
    float* csq = sm + 4352;   // [64] exact ||c_prev||^2
    float* w   = sm + 4416;   // [128][72] tf32 W tile
    float* att = sm + 13632;  // [128][72] fp32 attn
    float* cs  = sm + 22848;  // [64][64] fp32 g_clusters
    float* wsq = sm + 26944;  // [128]

    const int tid = threadIdx.x;
    const int lane = tid & 31, wid = tid >> 5;
    const int gid = lane >> 2, tig = lane & 3;
    const int m1 = wid * 16;
    const size_t row0 = (size_t)blockIdx.x * MT;

    for (int i = tid; i < KC * DIM; i += TPB) {
        cl[(i >> 6) * 68 + (i & 63)] = __uint_as_float(f2t(g_prev[i]));
        float cv = g_clusters[i];
        cs[i] = cv;
        if (blockIdx.x == 0) clus_out[i] = cv;
    }
    if (tid < KC) {
        float s = 0.f;
#pragma unroll
        for (int d = 0; d < DIM; d++) { float v = g_prev[tid * DIM + d]; s += v * v; }
        csq[tid] = s;
    }
    for (int i = tid * 4; i < MT * DIM; i += TPB * 4) {
        float4 v = *(const float4*)(W + row0 * DIM + i);
        v.x = __uint_as_float(f2t(v.x));
        v.y = __uint_as_float(f2t(v.y));
        v.z = __uint_as_float(f2t(v.z));
        v.w = __uint_as_float(f2t(v.w));
        *(float4*)(w + (i >> 6) * 72 + (i & 63)) = v;
    }
    if (tid < MT) wsq[tid] = g_wsq[row0 + tid];
    __syncthreads();

    // ---- GEMM1 (tf32 mma): C1[row][kc] = W * C_prev^T ----
    float c1[8][4];
#pragma unroll
    for (int j = 0; j < 8; j++) { c1[j][0] = c1[j][1] = c1[j][2] = c1[j][3] = 0.f; }
    const float* Ab = w + (m1 + gid) * 72 + tig;
#pragma unroll 4
    for (int s = 0; s < 8; s++) {
        const int k0 = 8 * s;
        uint32_t a0 = BITS(Ab[k0]);
        uint32_t a1 = BITS(Ab[8 * 72 + k0]);
        uint32_t a2 = BITS(Ab[k0 + 4]);
        uint32_t a3 = BITS(Ab[8 * 72 + k0 + 4]);
        const float* Bb = cl + gid * 68 + k0 + tig;
#pragma unroll
        for (int j = 0; j < 8; j++) {
            uint32_t b0 = BITS(Bb[j * 544]);
            uint32_t b1 = BITS(Bb[j * 544 + 4]);
            mma8(c1[j], a0, a1, a2, a3, b0, b1);
        }
    }

    // ---- softmax rows (fp32 attn into smem) ----
    {
        float ws = wsq[m1 + gid];
        float e[16], mn = 3.4e38f;
#pragma unroll
        for (int j = 0; j < 8; j++) {
            float2 cq = *(const float2*)(csq + 8 * j + 2 * tig);
            float d0 = fsqrt_fast(fmaxf(ws + cq.x - 2.f * c1[j][0], 0.f));
            float d1 = fsqrt_fast(fmaxf(ws + cq.y - 2.f * c1[j][1], 0.f));
            e[2 * j] = d0; e[2 * j + 1] = d1;
            mn = fminf(mn, fminf(d0, d1));
        }
        mn = fminf(mn, __shfl_xor_sync(0xffffffffu, mn, 1));
        mn = fminf(mn, __shfl_xor_sync(0xffffffffu, mn, 2));
        float s = 0.f;
#pragma unroll
        for (int j = 0; j < 16; j++) { e[j] = __expf(mn - e[j]); s += e[j]; }
        s += __shfl_xor_sync(0xffffffffu, s, 1);
        s += __shfl_xor_sync(0xffffffffu, s, 2);
        float inv = 1.f / s;
        float* wA = att + (m1 + gid) * 72 + 2 * tig;
#pragma unroll
        for (int j = 0; j < 8; j++)
            *(float2*)(wA + 8 * j) = make_float2(e[2 * j] * inv, e[2 * j + 1] * inv);
    }
    {
        float ws = wsq[m1 + gid + 8];
        float e[16], mn = 3.4e38f;
#pragma unroll
        for (int j = 0; j < 8; j++) {
            float2 cq = *(const float2*)(csq + 8 * j + 2 * tig);
            float d0 = fsqrt_fast(fmaxf(ws + cq.x - 2.f * c1[j][2], 0.f));
            float d1 = fsqrt_fast(fmaxf(ws + cq.y - 2.f * c1[j][3], 0.f));
            e[2 * j] = d0; e[2 * j + 1] = d1;
            mn = fminf(mn, fminf(d0, d1));
        }
        mn = fminf(mn, __shfl_xor_sync(0xffffffffu, mn, 1));
        mn = fminf(mn, __shfl_xor_sync(0xffffffffu, mn, 2));
        float s = 0.f;
#pragma unroll
        for (int j = 0; j < 16; j++) { e[j] = __expf(mn - e[j]); s += e[j]; }
        s += __shfl_xor_sync(0xffffffffu, s, 1);
        s += __shfl_xor_sync(0xffffffffu, s, 2);
        float inv = 1.f / s;
        float* wB = att + (m1 + gid + 8) * 72 + 2 * tig;
#pragma unroll
        for (int j = 0; j < 8; j++)
            *(float2*)(wB + 8 * j) = make_float2(e[2 * j] * inv, e[2 * j + 1] * inv);
    }
    __syncthreads();

    // ---- coalesced attn writeback ----
    for (int i = tid * 4; i < MT * KC; i += TPB * 4) {
        int r = i >> 6, c = i & 63;
        float4 v = *(float4*)(att + r * 72 + c);
        *(float4*)(attn_out + (row0 + r) * KC + c) = v;
    }

    // ---- GEMM3 (fp32 FFMA): comp = attn @ clusters ----
    {
        const int ty = tid >> 4, tx = tid & 15;
        const int i0 = ty * 8, d0 = tx * 4;
        float acc[8][4];
#pragma unroll
        for (int a = 0; a < 8; a++)
#pragma unroll
            for (int b = 0; b < 4; b++) acc[a][b] = 0.f;
#pragma unroll 4
        for (int k = 0; k < KC; k++) {
            float4 bv = *(float4*)(cs + k * 64 + d0);
#pragma unroll
            for (int ii = 0; ii < 8; ii++) {
                float a = att[(i0 + ii) * 72 + k];
                acc[ii][0] += a * bv.x;
                acc[ii][1] += a * bv.y;
                acc[ii][2] += a * bv.z;
                acc[ii][3] += a * bv.w;
            }
        }
#pragma unroll
        for (int ii = 0; ii < 8; ii++) {
            float4 v = {acc[ii][0], acc[ii][1], acc[ii][2], acc[ii][3]};
            *(float4*)(comp + (row0 + i0 + ii) * DIM + d0) = v;
        }
    }
}

// ---------------- launch ----------------
extern "C" void kernel_launch(void* const* d_in, const int* in_sizes, int n_in,
                              void* d_out, int out_size) {
    const float* W  = (const float*)d_in[0];
    const float* C0 = (const float*)d_in[1];
    float* out  = (float*)d_out;
    float* comp = out;                                    // [N, D]
    float* clus = out + (size_t)NROWS * DIM;              // [K, D]
    float* attn = clus + (size_t)KC * DIM;                // [N, K]

    int sms = 0;
    cudaDeviceGetAttribute(&sms, cudaDevAttrMultiProcessorCount, 0);
    if (sms <= 0 || sms > MAXGRID) sms = MAXGRID;
    const int grid_iter = 2 * sms;                        // 2 CTAs/SM, all resident

    const int smem_iter  = 22976 * (int)sizeof(float);    // 91904 B  -> occ 2
    const int smem_final = 27072 * (int)sizeof(float);    // 108288 B -> occ 2
    cudaFuncSetAttribute(iter_fused, cudaFuncAttributeMaxDynamicSharedMemorySize, smem_iter);
    cudaFuncSetAttribute(final_fused, cudaFuncAttributeMaxDynamicSharedMemorySize, smem_final);

    init_kernel<<<NROWS / TPB, TPB>>>(W, C0);
    for (int it = 0; it < ITERS; it++)
        iter_fused<<<grid_iter, TPB, smem_iter>>>(it, W);
    final_fused<<<NROWS / MT, TPB, smem_final>>>(W, attn, comp, clus);
}

// round 9
// speedup vs baseline: 2.4215x; 1.0002x over previous
#include <cuda_runtime.h>
#include <math.h>
#include <stdint.h>

#define NROWS 131072
#define DIM 64
#define KC 64
#define ITERS 10
#define TPB 256
#define MT 128                    // rows per tile
#define NT (NROWS / MT)           // 1024 tiles
#define MAXGRID 148
#define GRID_ITER 256             // divides NT exactly; <= 2*SMs resident slots
#define PSTR (64 * 68)            // floats per partial slot

// ---------------- device globals (no cudaMalloc allowed) ----------------
__device__ float g_clusters[KC * DIM];
__device__ float g_prev[KC * DIM];          // clusters used by last active iteration
__device__ float g_part[(size_t)(2 * MAXGRID) * PSTR];   // 1 slot per block
__device__ float g_normk[KC];
__device__ float g_wsq[NROWS];
__device__ int   g_done;
__device__ volatile int g_sync[2];

// ---------------- helpers ----------------
__device__ __forceinline__ uint32_t f2t(float x) {
    uint32_t u;
    asm("cvt.rna.tf32.f32 %0, %1;" : "=r"(u) : "f"(x));
    return u;
}
__device__ __forceinline__ float fsqrt_fast(float x) {
    float r;
    asm("sqrt.approx.f32 %0, %1;" : "=f"(r) : "f"(x));
    return r;
}
__device__ __forceinline__ void mma8(float c[4], uint32_t a0, uint32_t a1, uint32_t a2,
                                     uint32_t a3, uint32_t b0, uint32_t b1) {
    asm("mma.sync.aligned.m16n8k8.row.col.f32.tf32.tf32.f32 "
        "{%0,%1,%2,%3},{%4,%5,%6,%7},{%8,%9},{%0,%1,%2,%3};"
        : "+f"(c[0]), "+f"(c[1]), "+f"(c[2]), "+f"(c[3])
        : "r"(a0), "r"(a1), "r"(a2), "r"(a3), "r"(b0), "r"(b1));
}
#define BITS(x) (__float_as_uint(x))
// permuted cluster layout: clp[n*80 + (k&3)*20 + (k>>2)] -> float4 = 2 mma k-steps
#define CLP_POS(k) (((k) & 3) * 20 + ((k) >> 2))

// deterministic grid-wide sync: monotonic counters, per-launch target
__device__ __forceinline__ void gsync(int j, int target) {
    __syncthreads();
    if (threadIdx.x == 0) {
        __threadfence();
        atomicAdd((int*)&g_sync[j], 1);
        while (g_sync[j] < target) { }
        __threadfence();
    }
    __syncthreads();
}

// ---------------- init: flags, counters, cluster copy, ||w||^2 ----------------
__global__ void init_kernel(const float* __restrict__ W, const float* __restrict__ C0) {
    int gid = blockIdx.x * blockDim.x + threadIdx.x;   // NROWS threads
    if (gid == 0) { g_done = 0; g_sync[0] = 0; g_sync[1] = 0; }
    if (gid < KC * DIM) g_clusters[gid] = C0[gid];
    const float4* p = (const float4*)(W + (size_t)gid * DIM);
    float s = 0.f;
#pragma unroll
    for (int j = 0; j < 16; j++) {
        float4 v = p[j];
        s += v.x * v.x + v.y * v.y + v.z * v.z + v.w * v.w;
    }
    g_wsq[gid] = s;
}

// ---------------- fully fused iteration kernel (256 blocks, occ 2) ----------------
__global__ __launch_bounds__(TPB, 2) void iter_fused(int it, const float* __restrict__ W) {
    if (g_done) return;
    extern __shared__ float sm[];
    float* clp  = sm;          // [64][80] clusters, k-permuted tf32
    float* csq  = sm + 5120;   // [64] exact ||c||^2
    float* w    = sm + 5184;   // [128][72] W tile (tf32); col64=1, cols65-71=0
    float* att  = sm + 14400;  // [128][72] attn tile (tf32); reused as c2 stage at end
    float* wsqs = sm + 23616;  // [128]

    const int tid = threadIdx.x;
    const int lane = tid & 31, wid = tid >> 5;
    const int gid = lane >> 2, tig = lane & 3;
    const int m1 = wid * 16;            // GEMM1 row offset
    const int m2 = (wid & 3) * 16;      // GEMM2 kc offset
    const int rh = (wid >> 2) * 64;     // GEMM2 row-half offset
    const int target = (it + 1) * (int)gridDim.x;

    for (int i = tid; i < KC * DIM; i += TPB) {
        int n = i >> 6, k = i & 63;
        clp[n * 80 + CLP_POS(k)] = __uint_as_float(f2t(g_clusters[i]));
    }
    if (tid < KC) {
        float s = 0.f;
#pragma unroll
        for (int d = 0; d < DIM; d++) { float v = g_clusters[tid * DIM + d]; s += v * v; }
        csq[tid] = s;
    }
    // persistent ones/zeros in cols 64..71 of w (colsum trick)
    for (int i = tid; i < MT * 8; i += TPB) {
        int r = i >> 3, c = i & 7;
        w[r * 72 + 64 + c] = (c == 0) ? 1.0f : 0.0f;
    }

    float c2[9][4];
#pragma unroll
    for (int j = 0; j < 9; j++) { c2[j][0] = c2[j][1] = c2[j][2] = c2[j][3] = 0.f; }

    // ---- prefetch first tile into registers ----
    float4 rw[8];
    float wsq_pf = 0.f;
    {
        const float* src = W + (size_t)blockIdx.x * MT * DIM;
#pragma unroll
        for (int j = 0; j < 8; j++) rw[j] = *(const float4*)(src + tid * 4 + j * 1024);
        if (tid < MT) wsq_pf = g_wsq[(size_t)blockIdx.x * MT + tid];
    }

    for (int tile = blockIdx.x; tile < NT; tile += gridDim.x) {
        __syncthreads();   // w/att free (previous GEMM2 done; init done on first pass)
#pragma unroll
        for (int j = 0; j < 8; j++) {
            const int i = tid * 4 + j * 1024;
            float4 v = rw[j];
            v.x = __uint_as_float(f2t(v.x));
            v.y = __uint_as_float(f2t(v.y));
            v.z = __uint_as_float(f2t(v.z));
            v.w = __uint_as_float(f2t(v.w));
            *(float4*)(w + (i >> 6) * 72 + (i & 63)) = v;
        }
        if (tid < MT) wsqs[tid] = wsq_pf;
        __syncthreads();

        // issue prefetch for next tile (retires under GEMM1+softmax)
        const int nt = tile + (int)gridDim.x;
        if (nt < NT) {
            const float* src = W + (size_t)nt * MT * DIM;
#pragma unroll
            for (int j = 0; j < 8; j++) rw[j] = *(const float4*)(src + tid * 4 + j * 1024);
            if (tid < MT) wsq_pf = g_wsq[(size_t)nt * MT + tid];
        }

        // ---- GEMM1: C1[row][kc] = W * C^T  (B via vectorized permuted loads) ----
        float c1[8][4];
#pragma unroll
        for (int j = 0; j < 8; j++) { c1[j][0] = c1[j][1] = c1[j][2] = c1[j][3] = 0.f; }
        const float* Ab = w + (m1 + gid) * 72 + tig;
        const float* Bp = clp + gid * 80 + tig * 20;
#pragma unroll
        for (int t = 0; t < 4; t++) {
            const int k0 = 16 * t;
            uint32_t a00 = BITS(Ab[k0]),     a01 = BITS(Ab[576 + k0]);
            uint32_t a02 = BITS(Ab[k0 + 4]), a03 = BITS(Ab[576 + k0 + 4]);
            uint32_t a10 = BITS(Ab[k0 + 8]),  a11 = BITS(Ab[576 + k0 + 8]);
            uint32_t a12 = BITS(Ab[k0 + 12]), a13 = BITS(Ab[576 + k0 + 12]);
#pragma unroll
            for (int j = 0; j < 8; j++) {
                float4 b = *(const float4*)(Bp + j * 640 + 4 * t);
                mma8(c1[j], a00, a01, a02, a03, BITS(b.x), BITS(b.y));
                mma8(c1[j], a10, a11, a12, a13, BITS(b.z), BITS(b.w));
            }
        }

        // ---- softmax row A (m1+gid), then row B (m1+gid+8) ----
        {
            float ws = wsqs[m1 + gid];
            float e[16], mn = 3.4e38f;
#pragma unroll
            for (int j = 0; j < 8; j++) {
                float c0 = csq[8 * j + 2 * tig], c1v = csq[8 * j + 2 * tig + 1];
                float d0 = fsqrt_fast(fmaxf(ws + c0 - 2.f * c1[j][0], 0.f));
                float d1 = fsqrt_fast(fmaxf(ws + c1v - 2.f * c1[j][1], 0.f));
                e[2 * j] = d0; e[2 * j + 1] = d1;
                mn = fminf(mn, fminf(d0, d1));
            }
            mn = fminf(mn, __shfl_xor_sync(0xffffffffu, mn, 1));
            mn = fminf(mn, __shfl_xor_sync(0xffffffffu, mn, 2));
            float s = 0.f;
#pragma unroll
            for (int j = 0; j < 16; j++) { e[j] = __expf(mn - e[j]); s += e[j]; }
            s += __shfl_xor_sync(0xffffffffu, s, 1);
            s += __shfl_xor_sync(0xffffffffu, s, 2);
            float inv = 1.f / s;
            float* wA = att + (m1 + gid) * 72 + 2 * tig;
#pragma unroll
            for (int j = 0; j < 8; j++) {
                float2 v = make_float2(__uint_as_float(f2t(e[2 * j] * inv)),
                                       __uint_as_float(f2t(e[2 * j + 1] * inv)));
                *(float2*)(wA + 8 * j) = v;
            }
        }
        {
            float ws = wsqs[m1 + gid + 8];
            float e[16], mn = 3.4e38f;
#pragma unroll
            for (int j = 0; j < 8; j++) {
                float c0 = csq[8 * j + 2 * tig], c1v = csq[8 * j + 2 * tig + 1];
                float d0 = fsqrt_fast(fmaxf(ws + c0 - 2.f * c1[j][2], 0.f));
                float d1 = fsqrt_fast(fmaxf(ws + c1v - 2.f * c1[j][3], 0.f));
                e[2 * j] = d0; e[2 * j + 1] = d1;
                mn = fminf(mn, fminf(d0, d1));
            }
            mn = fminf(mn, __shfl_xor_sync(0xffffffffu, mn, 1));
            mn = fminf(mn, __shfl_xor_sync(0xffffffffu, mn, 2));
            float s = 0.f;
#pragma unroll
            for (int j = 0; j < 16; j++) { e[j] = __expf(mn - e[j]); s += e[j]; }
            s += __shfl_xor_sync(0xffffffffu, s, 1);
            s += __shfl_xor_sync(0xffffffffu, s, 2);
            float inv = 1.f / s;
            float* wB = att + (m1 + gid + 8) * 72 + 2 * tig;
#pragma unroll
            for (int j = 0; j < 8; j++) {
                float2 v = make_float2(__uint_as_float(f2t(e[2 * j] * inv)),
                                       __uint_as_float(f2t(e[2 * j + 1] * inv)));
                *(float2*)(wB + 8 * j) = v;
            }
        }
        __syncthreads();

        // ---- GEMM2: C2[kc][d] += attn^T * W  (9th n-frag vs ones col = colsum) ----
        const float* A2 = att + (rh + tig) * 72 + m2 + gid;
        const float* B2 = w + (rh + tig) * 72 + gid;
#pragma unroll 4
        for (int s = 0; s < 8; s++) {
            const int o = s * 8 * 72;
            uint32_t a0 = BITS(A2[o]);
            uint32_t a1 = BITS(A2[o + 8]);
            uint32_t a2 = BITS(A2[o + 4 * 72]);
            uint32_t a3 = BITS(A2[o + 4 * 72 + 8]);
#pragma unroll
            for (int j = 0; j < 9; j++) {
                uint32_t b0 = BITS(B2[o + 8 * j]);
                uint32_t b1 = BITS(B2[o + 4 * 72 + 8 * j]);
                mma8(c2[j], a0, a1, a2, a3, b0, b1);
            }
        }
    }

    // ---- combine row-halves in smem, write ONE partial slot per block ----
    __syncthreads();
    {
        float* stage = att;             // [64][72] c2 of row-half 1
        if (rh) {
#pragma unroll
            for (int j = 0; j < 8; j++) {
                *(float2*)(stage + (m2 + gid) * 72 + 8 * j + 2 * tig) = make_float2(c2[j][0], c2[j][1]);
                *(float2*)(stage + (m2 + gid + 8) * 72 + 8 * j + 2 * tig) = make_float2(c2[j][2], c2[j][3]);
            }
            if (tig == 0) {
                stage[(m2 + gid) * 72 + 64] = c2[8][0];
                stage[(m2 + gid + 8) * 72 + 64] = c2[8][2];
            }
        }
        __syncthreads();
        if (!rh) {
            float* P = g_part + (size_t)blockIdx.x * PSTR;
#pragma unroll
            for (int j = 0; j < 8; j++) {
                float2 s0 = *(float2*)(stage + (m2 + gid) * 72 + 8 * j + 2 * tig);
                float2 s1 = *(float2*)(stage + (m2 + gid + 8) * 72 + 8 * j + 2 * tig);
                *(float2*)(P + (m2 + gid) * 68 + 8 * j + 2 * tig) =
                    make_float2(c2[j][0] + s0.x, c2[j][1] + s0.y);
                *(float2*)(P + (m2 + gid + 8) * 68 + 8 * j + 2 * tig) =
                    make_float2(c2[j][2] + s1.x, c2[j][3] + s1.y);
            }
            if (tig == 0) {
                P[(m2 + gid) * 68 + 64] = c2[8][0] + stage[(m2 + gid) * 72 + 64];
                P[(m2 + gid + 8) * 68 + 64] = c2[8][2] + stage[(m2 + gid + 8) * 72 + 64];
            }
        }
    }

    gsync(0, target);

    // ---- blocks 0..63 reduce partials for their k ----
    float nv = 0.f, ov = 0.f;
    const int kblk = blockIdx.x;
    if (kblk < 64) {
        float* r_num = sm;          // [4][64]
        float* r_den = sm + 256;    // [4]
        float* s_nrm = sm + 264;    // [2]
        const int q = tid >> 6, d = tid & 63;
        const int nslots = (int)gridDim.x;
        float s = 0.f, sden = 0.f;
        const float* base = g_part + kblk * 68;
        for (int b = q; b < nslots; b += 4) {
            const float* P = base + (size_t)b * PSTR;
            s += P[d];
            if (d == 0) sden += P[64];
        }
        r_num[q * 64 + d] = s;
        if (d == 0) r_den[q] = sden;
        __syncthreads();
        if (tid < 64) {
            float num = (r_num[tid] + r_num[64 + tid]) + (r_num[128 + tid] + r_num[192 + tid]);
            float den = (r_den[0] + r_den[1]) + (r_den[2] + r_den[3]);
            nv = num / den;
            ov = g_clusters[kblk * 64 + tid];
            float x = (nv - ov) * (nv - ov);
#pragma unroll
            for (int o = 16; o > 0; o >>= 1) x += __shfl_xor_sync(0xffffffffu, x, o);
            if ((tid & 31) == 0) s_nrm[tid >> 5] = x;
        }
        __syncthreads();
        if (tid == 0) g_normk[kblk] = s_nrm[0] + s_nrm[1];
    }

    gsync(1, target);

    // ---- convergence decision (redundant per block) + commit ----
    if (kblk < 64) {
        __shared__ int s_conv;
        if (tid == 0) {
            float t = 0.f;
            for (int k = 0; k < 64; k++) t += g_normk[k];
            int conv = (sqrtf(t) <= 1e-4f) ? 1 : 0;
            s_conv = conv;
            if (kblk == 0 && conv) g_done = 1;   // freeze for remaining launches
        }
        __syncthreads();
        if (tid < 64) {
            g_prev[kblk * 64 + tid] = ov;
            g_clusters[kblk * 64 + tid] = s_conv ? ov : nv;
        }
    }
}

// ---------------- fused final: attn (tf32 GEMM1 + fp32 softmax) + compressed + clusters ----------------
__global__ __launch_bounds__(TPB, 2) void final_fused(const float* __restrict__ W,
                                                      float* __restrict__ attn_out,
                                                      float* __restrict__ comp,
                                                      float* __restrict__ clus_out) {
    extern __shared__ float sm[];
    float* clp = sm;          // [64][80] tf32(g_prev), k-permuted
    float* csq = sm + 5120;   // [64] exact ||c_prev||^2
    float* w   = sm + 5184;   // [128][72] tf32 W tile
    float* att = sm + 14400;  // [128][72] fp32 attn
    float* cs  = sm + 23616;  // [64][64] fp32 g_clusters
    float* wsq = sm + 27712;  // [128]

    const int tid = threadIdx.x;
    const int lane = tid & 31, wid = tid >> 5;
    const int gid = lane >> 2, tig = lane & 3;
    const int m1 = wid * 16;
    const size_t row0 = (size_t)blockIdx.x * MT;

    for (int i = tid; i < KC * DIM; i += TPB) {
        int n = i >> 6, k = i & 63;
        clp[n * 80 + CLP_POS(k)] = __uint_as_float(f2t(g_prev[i]));
        float cv = g_clusters[i];
        cs[i] = cv;
        if (blockIdx.x == 0) clus_out[i] = cv;
    }
    if (tid < KC) {
        float s = 0.f;
#pragma unroll
        for (int d = 0; d < DIM; d++) { float v = g_prev[tid * DIM + d]; s += v * v; }
        csq[tid] = s;
    }
    for (int i = tid * 4; i < MT * DIM; i += TPB * 4) {
        float4 v = *(const float4*)(W + row0 * DIM + i);
        v.x = __uint_as_float(f2t(v.x));
        v.y = __uint_as_float(f2t(v.y));
        v.z = __uint_as_float(f2t(v.z));
        v.w = __uint_as_float(f2t(v.w));
        *(float4*)(w + (i >> 6) * 72 + (i & 63)) = v;
    }
    if (tid < MT) wsq[tid] = g_wsq[row0 + tid];
    __syncthreads();

    // ---- GEMM1 (tf32 mma, vectorized B): C1[row][kc] = W * C_prev^T ----
    float c1[8][4];
#pragma unroll
    for (int j = 0; j < 8; j++) { c1[j][0] = c1[j][1] = c1[j][2] = c1[j][3] = 0.f; }
    const float* Ab = w + (m1 + gid) * 72 + tig;
    const float* Bp = clp + gid * 80 + tig * 20;
#pragma unroll
    for (int t = 0; t < 4; t++) {
        const int k0 = 16 * t;
        uint32_t a00 = BITS(Ab[k0]),     a01 = BITS(Ab[576 + k0]);
        uint32_t a02 = BITS(Ab[k0 + 4]), a03 = BITS(Ab[576 + k0 + 4]);
        uint32_t a10 = BITS(Ab[k0 + 8]),  a11 = BITS(Ab[576 + k0 + 8]);
        uint32_t a12 = BITS(Ab[k0 + 12]), a13 = BITS(Ab[576 + k0 + 12]);
#pragma unroll
        for (int j = 0; j < 8; j++) {
            float4 b = *(const float4*)(Bp + j * 640 + 4 * t);
            mma8(c1[j], a00, a01, a02, a03, BITS(b.x), BITS(b.y));
            mma8(c1[j], a10, a11, a12, a13, BITS(b.z), BITS(b.w));
        }
    }

    // ---- softmax rows (fp32 attn into smem) ----
    {
        float ws = wsq[m1 + gid];
        float e[16], mn = 3.4e38f;
#pragma unroll
        for (int j = 0; j < 8; j++) {
            float c0 = csq[8 * j + 2 * tig], c1v = csq[8 * j + 2 * tig + 1];
            float d0 = fsqrt_fast(fmaxf(ws + c0 - 2.f * c1[j][0], 0.f));
            float d1 = fsqrt_fast(fmaxf(ws + c1v - 2.f * c1[j][1], 0.f));
            e[2 * j] = d0; e[2 * j + 1] = d1;
            mn = fminf(mn, fminf(d0, d1));
        }
        mn = fminf(mn, __shfl_xor_sync(0xffffffffu, mn, 1));
        mn = fminf(mn, __shfl_xor_sync(0xffffffffu, mn, 2));
        float s = 0.f;
#pragma unroll
        for (int j = 0; j < 16; j++) { e[j] = __expf(mn - e[j]); s += e[j]; }
        s += __shfl_xor_sync(0xffffffffu, s, 1);
        s += __shfl_xor_sync(0xffffffffu, s, 2);
        float inv = 1.f / s;
        float* wA = att + (m1 + gid) * 72 + 2 * tig;
#pragma unroll
        for (int j = 0; j < 8; j++)
            *(float2*)(wA + 8 * j) = make_float2(e[2 * j] * inv, e[2 * j + 1] * inv);
    }
    {
        float ws = wsq[m1 + gid + 8];
        float e[16], mn = 3.4e38f;
#pragma unroll
        for (int j = 0; j < 8; j++) {
            float c0 = csq[8 * j + 2 * tig], c1v = csq[8 * j + 2 * tig + 1];
            float d0 = fsqrt_fast(fmaxf(ws + c0 - 2.f * c1[j][2], 0.f));
            float d1 = fsqrt_fast(fmaxf(ws + c1v - 2.f * c1[j][3], 0.f));
            e[2 * j] = d0; e[2 * j + 1] = d1;
            mn = fminf(mn, fminf(d0, d1));
        }
        mn = fminf(mn, __shfl_xor_sync(0xffffffffu, mn, 1));
        mn = fminf(mn, __shfl_xor_sync(0xffffffffu, mn, 2));
        float s = 0.f;
#pragma unroll
        for (int j = 0; j < 16; j++) { e[j] = __expf(mn - e[j]); s += e[j]; }
        s += __shfl_xor_sync(0xffffffffu, s, 1);
        s += __shfl_xor_sync(0xffffffffu, s, 2);
        float inv = 1.f / s;
        float* wB = att + (m1 + gid + 8) * 72 + 2 * tig;
#pragma unroll
        for (int j = 0; j < 8; j++)
            *(float2*)(wB + 8 * j) = make_float2(e[2 * j] * inv, e[2 * j + 1] * inv);
    }
    __syncthreads();

    // ---- coalesced attn writeback ----
    for (int i = tid * 4; i < MT * KC; i += TPB * 4) {
        int r = i >> 6, c = i & 63;
        float4 v = *(float4*)(att + r * 72 + c);
        *(float4*)(attn_out + (row0 + r) * KC + c) = v;
    }

    // ---- GEMM3 (fp32 FFMA): comp = attn @ clusters ----
    {
        const int ty = tid >> 4, tx = tid & 15;
        const int i0 = ty * 8, d0 = tx * 4;
        float acc[8][4];
#pragma unroll
        for (int a = 0; a < 8; a++)
#pragma unroll
            for (int b = 0; b < 4; b++) acc[a][b] = 0.f;
#pragma unroll 4
        for (int k = 0; k < KC; k++) {
            float4 bv = *(float4*)(cs + k * 64 + d0);
#pragma unroll
            for (int ii = 0; ii < 8; ii++) {
                float a = att[(i0 + ii) * 72 + k];
                acc[ii][0] += a * bv.x;
                acc[ii][1] += a * bv.y;
                acc[ii][2] += a * bv.z;
                acc[ii][3] += a * bv.w;
            }
        }
#pragma unroll
        for (int ii = 0; ii < 8; ii++) {
            float4 v = {acc[ii][0], acc[ii][1], acc[ii][2], acc[ii][3]};
            *(float4*)(comp + (row0 + i0 + ii) * DIM + d0) = v;
        }
    }
}

// ---------------- launch ----------------
extern "C" void kernel_launch(void* const* d_in, const int* in_sizes, int n_in,
                              void* d_out, int out_size) {
    const float* W  = (const float*)d_in[0];
    const float* C0 = (const float*)d_in[1];
    float* out  = (float*)d_out;
    float* comp = out;                                    // [N, D]
    float* clus = out + (size_t)NROWS * DIM;              // [K, D]
    float* attn = clus + (size_t)KC * DIM;                // [N, K]

    int sms = 0;
    cudaDeviceGetAttribute(&sms, cudaDevAttrMultiProcessorCount, 0);
    if (sms <= 0 || sms > MAXGRID) sms = MAXGRID;
    // perfectly balanced grid: GRID_ITER divides NT; must fit in 2 CTAs/SM residency
    int grid_iter = GRID_ITER;
    if (2 * sms < GRID_ITER) grid_iter = 2 * sms;         // fallback (still correct)

    const int smem_iter  = 23744 * (int)sizeof(float);    // 94976 B  -> occ 2
    const int smem_final = 27840 * (int)sizeof(float);    // 111360 B -> occ 2
    cudaFuncSetAttribute(iter_fused, cudaFuncAttributeMaxDynamicSharedMemorySize, smem_iter);
    cudaFuncSetAttribute(final_fused, cudaFuncAttributeMaxDynamicSharedMemorySize, smem_final);

    init_kernel<<<NROWS / TPB, TPB>>>(W, C0);
    for (int it = 0; it < ITERS; it++)
        iter_fused<<<grid_iter, TPB, smem_iter>>>(it, W);
    final_fused<<<NROWS / MT, TPB, smem_final>>>(W, attn, comp, clus);
}

// round 11
// speedup vs baseline: 2.5076x; 1.0355x over previous
#include <cuda_runtime.h>
#include <math.h>
#include <stdint.h>

#define NROWS 131072
#define DIM 64
#define KC 64
#define ITERS 10
#define TPB 256
#define MT 128                    // rows per tile
#define NT (NROWS / MT)           // 1024 tiles
#define MAXGRID 148
#define PSTR (64 * 68)            // floats per partial slot

// ---------------- device globals (no cudaMalloc allowed) ----------------
__device__ float g_clusters[KC * DIM];
__device__ float g_prev[KC * DIM];          // clusters used by last active iteration
__device__ float g_part[(size_t)(2 * MAXGRID) * PSTR];   // 1 slot per block
__device__ float g_normk[KC];
__device__ float g_wsq[NROWS];
__device__ int   g_done;
__device__ volatile int g_sync[2];

// ---------------- helpers ----------------
__device__ __forceinline__ uint32_t f2t(float x) {
    uint32_t u;
    asm("cvt.rna.tf32.f32 %0, %1;" : "=r"(u) : "f"(x));
    return u;
}
__device__ __forceinline__ float fsqrt_fast(float x) {
    float r;
    asm("sqrt.approx.f32 %0, %1;" : "=f"(r) : "f"(x));
    return r;
}
__device__ __forceinline__ void mma8(float c[4], uint32_t a0, uint32_t a1, uint32_t a2,
                                     uint32_t a3, uint32_t b0, uint32_t b1) {
    asm("mma.sync.aligned.m16n8k8.row.col.f32.tf32.tf32.f32 "
        "{%0,%1,%2,%3},{%4,%5,%6,%7},{%8,%9},{%0,%1,%2,%3};"
        : "+f"(c[0]), "+f"(c[1]), "+f"(c[2]), "+f"(c[3])
        : "r"(a0), "r"(a1), "r"(a2), "r"(a3), "r"(b0), "r"(b1));
}
#define BITS(x) (__float_as_uint(x))
// permuted k layout: pos(k) = (k&3)*20 + (k>>2), row stride 80 -> float4 = 2 mma k-steps
#define CLP_POS(k) (((k) & 3) * 20 + ((k) >> 2))

// deterministic grid-wide sync: monotonic counters, per-launch target
__device__ __forceinline__ void gsync(int j, int target) {
    __syncthreads();
    if (threadIdx.x == 0) {
        __threadfence();
        atomicAdd((int*)&g_sync[j], 1);
        while (g_sync[j] < target) { }
        __threadfence();
    }
    __syncthreads();
}

// ---------------- init: flags, counters, cluster copy, ||w||^2 ----------------
__global__ void init_kernel(const float* __restrict__ W, const float* __restrict__ C0) {
    int gid = blockIdx.x * blockDim.x + threadIdx.x;   // NROWS threads
    if (gid == 0) { g_done = 0; g_sync[0] = 0; g_sync[1] = 0; }
    if (gid < KC * DIM) g_clusters[gid] = C0[gid];
    const float4* p = (const float4*)(W + (size_t)gid * DIM);
    float s = 0.f;
#pragma unroll
    for (int j = 0; j < 16; j++) {
        float4 v = p[j];
        s += v.x * v.x + v.y * v.y + v.z * v.z + v.w * v.w;
    }
    g_wsq[gid] = s;
}

// ---------------- fully fused iteration kernel (296 blocks, occ 2) ----------------
__global__ __launch_bounds__(TPB, 2) void iter_fused(int it, const float* __restrict__ W) {
    if (g_done) return;
    extern __shared__ float sm[];
    float* clp  = sm;          // [64][80] clusters, k-permuted tf32
    float* csq  = sm + 5120;   // [64] exact ||c||^2
    float* w    = sm + 5184;   // [128][72] W tile (tf32); col64=1, cols65-71=0
    float* att  = sm + 14400;  // [128][72] attn tile (tf32); reused as c2 stage at end
    float* wsqs = sm + 23616;  // [128]

    const int tid = threadIdx.x;
    const int lane = tid & 31, wid = tid >> 5;
    const int gid = lane >> 2, tig = lane & 3;
    const int m1 = wid * 16;            // GEMM1 row offset
    const int m2 = (wid & 3) * 16;      // GEMM2 kc offset
    const int rh = (wid >> 2) * 64;     // GEMM2 row-half offset
    const int target = (it + 1) * (int)gridDim.x;

    for (int i = tid; i < KC * DIM; i += TPB) {
        int n = i >> 6, k = i & 63;
        clp[n * 80 + CLP_POS(k)] = __uint_as_float(f2t(g_clusters[i]));
    }
    if (tid < KC) {
        float s = 0.f;
#pragma unroll
        for (int d = 0; d < DIM; d++) { float v = g_clusters[tid * DIM + d]; s += v * v; }
        csq[tid] = s;
    }
    // persistent ones/zeros in cols 64..71 of w (colsum trick)
    for (int i = tid; i < MT * 8; i += TPB) {
        int r = i >> 3, c = i & 7;
        w[r * 72 + 64 + c] = (c == 0) ? 1.0f : 0.0f;
    }

    float c2[9][4];
#pragma unroll
    for (int j = 0; j < 9; j++) { c2[j][0] = c2[j][1] = c2[j][2] = c2[j][3] = 0.f; }

    // ---- prefetch first tile into registers ----
    float4 rw[8];
    float wsq_pf = 0.f;
    {
        const float* src = W + (size_t)blockIdx.x * MT * DIM;
#pragma unroll
        for (int j = 0; j < 8; j++) rw[j] = *(const float4*)(src + tid * 4 + j * 1024);
        if (tid < MT) wsq_pf = g_wsq[(size_t)blockIdx.x * MT + tid];
    }

    for (int tile = blockIdx.x; tile < NT; tile += gridDim.x) {
        __syncthreads();   // w/att free (previous GEMM2 done; init done on first pass)
#pragma unroll
        for (int j = 0; j < 8; j++) {
            const int i = tid * 4 + j * 1024;
            float4 v = rw[j];
            v.x = __uint_as_float(f2t(v.x));
            v.y = __uint_as_float(f2t(v.y));
            v.z = __uint_as_float(f2t(v.z));
            v.w = __uint_as_float(f2t(v.w));
            *(float4*)(w + (i >> 6) * 72 + (i & 63)) = v;
        }
        if (tid < MT) wsqs[tid] = wsq_pf;
        __syncthreads();

        // issue prefetch for next tile (retires under GEMM1+softmax)
        const int nt = tile + (int)gridDim.x;
        if (nt < NT) {
            const float* src = W + (size_t)nt * MT * DIM;
#pragma unroll
            for (int j = 0; j < 8; j++) rw[j] = *(const float4*)(src + tid * 4 + j * 1024);
            if (tid < MT) wsq_pf = g_wsq[(size_t)nt * MT + tid];
        }

        // ---- GEMM1: C1[row][kc] = W * C^T  (B via vectorized permuted loads) ----
        float c1[8][4];
#pragma unroll
        for (int j = 0; j < 8; j++) { c1[j][0] = c1[j][1] = c1[j][2] = c1[j][3] = 0.f; }
        const float* Ab = w + (m1 + gid) * 72 + tig;
        const float* Bp = clp + gid * 80 + tig * 20;
#pragma unroll
        for (int t = 0; t < 4; t++) {
            const int k0 = 16 * t;
            uint32_t a00 = BITS(Ab[k0]),     a01 = BITS(Ab[576 + k0]);
            uint32_t a02 = BITS(Ab[k0 + 4]), a03 = BITS(Ab[576 + k0 + 4]);
            uint32_t a10 = BITS(Ab[k0 + 8]),  a11 = BITS(Ab[576 + k0 + 8]);
            uint32_t a12 = BITS(Ab[k0 + 12]), a13 = BITS(Ab[576 + k0 + 12]);
#pragma unroll
            for (int j = 0; j < 8; j++) {
                float4 b = *(const float4*)(Bp + j * 640 + 4 * t);
                mma8(c1[j], a00, a01, a02, a03, BITS(b.x), BITS(b.y));
                mma8(c1[j], a10, a11, a12, a13, BITS(b.z), BITS(b.w));
            }
        }

        // ---- softmax row A (m1+gid), then row B (m1+gid+8) ----
        {
            float ws = wsqs[m1 + gid];
            float e[16], mn = 3.4e38f;
#pragma unroll
            for (int j = 0; j < 8; j++) {
                float c0 = csq[8 * j + 2 * tig], c1v = csq[8 * j + 2 * tig + 1];
                float d0 = fsqrt_fast(fmaxf(ws + c0 - 2.f * c1[j][0], 0.f));
                float d1 = fsqrt_fast(fmaxf(ws + c1v - 2.f * c1[j][1], 0.f));
                e[2 * j] = d0; e[2 * j + 1] = d1;
                mn = fminf(mn, fminf(d0, d1));
            }
            mn = fminf(mn, __shfl_xor_sync(0xffffffffu, mn, 1));
            mn = fminf(mn, __shfl_xor_sync(0xffffffffu, mn, 2));
            float s = 0.f;
#pragma unroll
            for (int j = 0; j < 16; j++) { e[j] = __expf(mn - e[j]); s += e[j]; }
            s += __shfl_xor_sync(0xffffffffu, s, 1);
            s += __shfl_xor_sync(0xffffffffu, s, 2);
            float inv = 1.f / s;
            float* wA = att + (m1 + gid) * 72 + 2 * tig;
#pragma unroll
            for (int j = 0; j < 8; j++) {
                float2 v = make_float2(__uint_as_float(f2t(e[2 * j] * inv)),
                                       __uint_as_float(f2t(e[2 * j + 1] * inv)));
                *(float2*)(wA + 8 * j) = v;
            }
        }
        {
            float ws = wsqs[m1 + gid + 8];
            float e[16], mn = 3.4e38f;
#pragma unroll
            for (int j = 0; j < 8; j++) {
                float c0 = csq[8 * j + 2 * tig], c1v = csq[8 * j + 2 * tig + 1];
                float d0 = fsqrt_fast(fmaxf(ws + c0 - 2.f * c1[j][2], 0.f));
                float d1 = fsqrt_fast(fmaxf(ws + c1v - 2.f * c1[j][3], 0.f));
                e[2 * j] = d0; e[2 * j + 1] = d1;
                mn = fminf(mn, fminf(d0, d1));
            }
            mn = fminf(mn, __shfl_xor_sync(0xffffffffu, mn, 1));
            mn = fminf(mn, __shfl_xor_sync(0xffffffffu, mn, 2));
            float s = 0.f;
#pragma unroll
            for (int j = 0; j < 16; j++) { e[j] = __expf(mn - e[j]); s += e[j]; }
            s += __shfl_xor_sync(0xffffffffu, s, 1);
            s += __shfl_xor_sync(0xffffffffu, s, 2);
            float inv = 1.f / s;
            float* wB = att + (m1 + gid + 8) * 72 + 2 * tig;
#pragma unroll
            for (int j = 0; j < 8; j++) {
                float2 v = make_float2(__uint_as_float(f2t(e[2 * j] * inv)),
                                       __uint_as_float(f2t(e[2 * j + 1] * inv)));
                *(float2*)(wB + 8 * j) = v;
            }
        }
        __syncthreads();

        // ---- GEMM2: C2[kc][d] += attn^T * W  (9th n-frag vs ones col = colsum) ----
        const float* A2 = att + (rh + tig) * 72 + m2 + gid;
        const float* B2 = w + (rh + tig) * 72 + gid;
#pragma unroll 4
        for (int s = 0; s < 8; s++) {
            const int o = s * 8 * 72;
            uint32_t a0 = BITS(A2[o]);
            uint32_t a1 = BITS(A2[o + 8]);
            uint32_t a2 = BITS(A2[o + 4 * 72]);
            uint32_t a3 = BITS(A2[o + 4 * 72 + 8]);
#pragma unroll
            for (int j = 0; j < 9; j++) {
                uint32_t b0 = BITS(B2[o + 8 * j]);
                uint32_t b1 = BITS(B2[o + 4 * 72 + 8 * j]);
                mma8(c2[j], a0, a1, a2, a3, b0, b1);
            }
        }
    }

    // ---- combine row-halves in smem, write ONE partial slot per block ----
    __syncthreads();
    {
        float* stage = att;             // [64][72] c2 of row-half 1
        if (rh) {
#pragma unroll
            for (int j = 0; j < 8; j++) {
                *(float2*)(stage + (m2 + gid) * 72 + 8 * j + 2 * tig) = make_float2(c2[j][0], c2[j][1]);
                *(float2*)(stage + (m2 + gid + 8) * 72 + 8 * j + 2 * tig) = make_float2(c2[j][2], c2[j][3]);
            }
            if (tig == 0) {
                stage[(m2 + gid) * 72 + 64] = c2[8][0];
                stage[(m2 + gid + 8) * 72 + 64] = c2[8][2];
            }
        }
        __syncthreads();
        if (!rh) {
            float* P = g_part + (size_t)blockIdx.x * PSTR;
#pragma unroll
            for (int j = 0; j < 8; j++) {
                float2 s0 = *(float2*)(stage + (m2 + gid) * 72 + 8 * j + 2 * tig);
                float2 s1 = *(float2*)(stage + (m2 + gid + 8) * 72 + 8 * j + 2 * tig);
                *(float2*)(P + (m2 + gid) * 68 + 8 * j + 2 * tig) =
                    make_float2(c2[j][0] + s0.x, c2[j][1] + s0.y);
                *(float2*)(P + (m2 + gid + 8) * 68 + 8 * j + 2 * tig) =
                    make_float2(c2[j][2] + s1.x, c2[j][3] + s1.y);
            }
            if (tig == 0) {
                P[(m2 + gid) * 68 + 64] = c2[8][0] + stage[(m2 + gid) * 72 + 64];
                P[(m2 + gid + 8) * 68 + 64] = c2[8][2] + stage[(m2 + gid + 8) * 72 + 64];
            }
        }
    }

    gsync(0, target);

    // ---- blocks 0..63 reduce partials for their k ----
    float nv = 0.f, ov = 0.f;
    const int kblk = blockIdx.x;
    if (kblk < 64) {
        float* r_num = sm;          // [4][64]
        float* r_den = sm + 256;    // [4]
        float* s_nrm = sm + 264;    // [2]
        const int q = tid >> 6, d = tid & 63;
        const int nslots = (int)gridDim.x;
        float s = 0.f, sden = 0.f;
        const float* base = g_part + kblk * 68;
        for (int b = q; b < nslots; b += 4) {
            const float* P = base + (size_t)b * PSTR;
            s += P[d];
            if (d == 0) sden += P[64];
        }
        r_num[q * 64 + d] = s;
        if (d == 0) r_den[q] = sden;
        __syncthreads();
        if (tid < 64) {
            float num = (r_num[tid] + r_num[64 + tid]) + (r_num[128 + tid] + r_num[192 + tid]);
            float den = (r_den[0] + r_den[1]) + (r_den[2] + r_den[3]);
            nv = num / den;
            ov = g_clusters[kblk * 64 + tid];
            float x = (nv - ov) * (nv - ov);
#pragma unroll
            for (int o = 16; o > 0; o >>= 1) x += __shfl_xor_sync(0xffffffffu, x, o);
            if ((tid & 31) == 0) s_nrm[tid >> 5] = x;
        }
        __syncthreads();
        if (tid == 0) g_normk[kblk] = s_nrm[0] + s_nrm[1];
    }

    gsync(1, target);

    // ---- convergence decision (redundant per block) + commit ----
    if (kblk < 64) {
        __shared__ int s_conv;
        if (tid == 0) {
            float t = 0.f;
            for (int k = 0; k < 64; k++) t += g_normk[k];
            int conv = (sqrtf(t) <= 1e-4f) ? 1 : 0;
            s_conv = conv;
            if (kblk == 0 && conv) g_done = 1;   // freeze for remaining launches
        }
        __syncthreads();
        if (tid < 64) {
            g_prev[kblk * 64 + tid] = ov;
            g_clusters[kblk * 64 + tid] = s_conv ? ov : nv;
        }
    }
}

// ---------------- fused final: attn (tf32 GEMM1 + fp32 softmax) + compressed (tf32 GEMM3) ----------------
__global__ __launch_bounds__(TPB, 2) void final_fused(const float* __restrict__ W,
                                                      float* __restrict__ attn_out,
                                                      float* __restrict__ comp,
                                                      float* __restrict__ clus_out) {
    extern __shared__ float sm[];
    float* clp = sm;          // [64][80] tf32(g_prev), k-permuted (B of GEMM1)
    float* csq = sm + 5120;   // [64] exact ||c_prev||^2
    float* w   = sm + 5184;   // [128][72] tf32 W tile
    float* att = sm + 14400;  // [128][72] fp32 attn
    float* csp = sm + 23616;  // [64][80] tf32(g_clusters), d-major k-permuted (B of GEMM3)
    float* wsq = sm + 28736;  // [128]

    const int tid = threadIdx.x;
    const int lane = tid & 31, wid = tid >> 5;
    const int gid = lane >> 2, tig = lane & 3;
    const int m1 = wid * 16;
    const size_t row0 = (size_t)blockIdx.x * MT;

    for (int i = tid; i < KC * DIM; i += TPB) {
        int kc = i >> 6, d = i & 63;
        clp[kc * 80 + CLP_POS(d)] = __uint_as_float(f2t(g_prev[i]));      // B1[n=kc][k=d]
        float cv = g_clusters[i];
        csp[d * 80 + CLP_POS(kc)] = __uint_as_float(f2t(cv));             // B3[n=d][k=kc]
        if (blockIdx.x == 0) clus_out[i] = cv;
    }
    if (tid < KC) {
        float s = 0.f;
#pragma unroll
        for (int d = 0; d < DIM; d++) { float v = g_prev[tid * DIM + d]; s += v * v; }
        csq[tid] = s;
    }
    for (int i = tid * 4; i < MT * DIM; i += TPB * 4) {
        float4 v = *(const float4*)(W + row0 * DIM + i);
        v.x = __uint_as_float(f2t(v.x));
        v.y = __uint_as_float(f2t(v.y));
        v.z = __uint_as_float(f2t(v.z));
        v.w = __uint_as_float(f2t(v.w));
        *(float4*)(w + (i >> 6) * 72 + (i & 63)) = v;
    }
    if (tid < MT) wsq[tid] = g_wsq[row0 + tid];
    __syncthreads();

    // ---- GEMM1 (tf32 mma, vectorized B): C1[row][kc] = W * C_prev^T ----
    float c1[8][4];
#pragma unroll
    for (int j = 0; j < 8; j++) { c1[j][0] = c1[j][1] = c1[j][2] = c1[j][3] = 0.f; }
    {
        const float* Ab = w + (m1 + gid) * 72 + tig;
        const float* Bp = clp + gid * 80 + tig * 20;
#pragma unroll
        for (int t = 0; t < 4; t++) {
            const int k0 = 16 * t;
            uint32_t a00 = BITS(Ab[k0]),     a01 = BITS(Ab[576 + k0]);
            uint32_t a02 = BITS(Ab[k0 + 4]), a03 = BITS(Ab[576 + k0 + 4]);
            uint32_t a10 = BITS(Ab[k0 + 8]),  a11 = BITS(Ab[576 + k0 + 8]);
            uint32_t a12 = BITS(Ab[k0 + 12]), a13 = BITS(Ab[576 + k0 + 12]);
#pragma unroll
            for (int j = 0; j < 8; j++) {
                float4 b = *(const float4*)(Bp + j * 640 + 4 * t);
                mma8(c1[j], a00, a01, a02, a03, BITS(b.x), BITS(b.y));
                mma8(c1[j], a10, a11, a12, a13, BITS(b.z), BITS(b.w));
            }
        }
    }

    // ---- softmax rows (fp32 attn into smem) ----
    {
        float ws = wsq[m1 + gid];
        float e[16], mn = 3.4e38f;
#pragma unroll
        for (int j = 0; j < 8; j++) {
            float c0 = csq[8 * j + 2 * tig], c1v = csq[8 * j + 2 * tig + 1];
            float d0 = fsqrt_fast(fmaxf(ws + c0 - 2.f * c1[j][0], 0.f));
            float d1 = fsqrt_fast(fmaxf(ws + c1v - 2.f * c1[j][1], 0.f));
            e[2 * j] = d0; e[2 * j + 1] = d1;
            mn = fminf(mn, fminf(d0, d1));
        }
        mn = fminf(mn, __shfl_xor_sync(0xffffffffu, mn, 1));
        mn = fminf(mn, __shfl_xor_sync(0xffffffffu, mn, 2));
        float s = 0.f;
#pragma unroll
        for (int j = 0; j < 16; j++) { e[j] = __expf(mn - e[j]); s += e[j]; }
        s += __shfl_xor_sync(0xffffffffu, s, 1);
        s += __shfl_xor_sync(0xffffffffu, s, 2);
        float inv = 1.f / s;
        float* wA = att + (m1 + gid) * 72 + 2 * tig;
#pragma unroll
        for (int j = 0; j < 8; j++)
            *(float2*)(wA + 8 * j) = make_float2(e[2 * j] * inv, e[2 * j + 1] * inv);
    }
    {
        float ws = wsq[m1 + gid + 8];
        float e[16], mn = 3.4e38f;
#pragma unroll
        for (int j = 0; j < 8; j++) {
            float c0 = csq[8 * j + 2 * tig], c1v = csq[8 * j + 2 * tig + 1];
            float d0 = fsqrt_fast(fmaxf(ws + c0 - 2.f * c1[j][2], 0.f));
            float d1 = fsqrt_fast(fmaxf(ws + c1v - 2.f * c1[j][3], 0.f));
            e[2 * j] = d0; e[2 * j + 1] = d1;
            mn = fminf(mn, fminf(d0, d1));
        }
        mn = fminf(mn, __shfl_xor_sync(0xffffffffu, mn, 1));
        mn = fminf(mn, __shfl_xor_sync(0xffffffffu, mn, 2));
        float s = 0.f;
#pragma unroll
        for (int j = 0; j < 16; j++) { e[j] = __expf(mn - e[j]); s += e[j]; }
        s += __shfl_xor_sync(0xffffffffu, s, 1);
        s += __shfl_xor_sync(0xffffffffu, s, 2);
        float inv = 1.f / s;
        float* wB = att + (m1 + gid + 8) * 72 + 2 * tig;
#pragma unroll
        for (int j = 0; j < 8; j++)
            *(float2*)(wB + 8 * j) = make_float2(e[2 * j] * inv, e[2 * j + 1] * inv);
    }
    __syncthreads();

    // ---- coalesced attn writeback ----
    for (int i = tid * 4; i < MT * KC; i += TPB * 4) {
        int r = i >> 6, c = i & 63;
        float4 v = *(float4*)(att + r * 72 + c);
        *(float4*)(attn_out + (row0 + r) * KC + c) = v;
    }

    // ---- GEMM3 (tf32 mma): comp[row][d] = attn @ clusters ----
    {
        float c3[8][4];
#pragma unroll
        for (int j = 0; j < 8; j++) { c3[j][0] = c3[j][1] = c3[j][2] = c3[j][3] = 0.f; }
        const float* Aa = att + (m1 + gid) * 72 + tig;     // rows m1+gid / +8, k = kc
        const float* Bp = csp + gid * 80 + tig * 20;
#pragma unroll
        for (int t = 0; t < 4; t++) {
            const int k0 = 16 * t;
            uint32_t a00 = f2t(Aa[k0]),      a01 = f2t(Aa[576 + k0]);
            uint32_t a02 = f2t(Aa[k0 + 4]),  a03 = f2t(Aa[576 + k0 + 4]);
            uint32_t a10 = f2t(Aa[k0 + 8]),  a11 = f2t(Aa[576 + k0 + 8]);
            uint32_t a12 = f2t(Aa[k0 + 12]), a13 = f2t(Aa[576 + k0 + 12]);
#pragma unroll
            for (int j = 0; j < 8; j++) {
                float4 b = *(const float4*)(Bp + j * 640 + 4 * t);
                mma8(c3[j], a00, a01, a02, a03, BITS(b.x), BITS(b.y));
                mma8(c3[j], a10, a11, a12, a13, BITS(b.z), BITS(b.w));
            }
        }
        // write: c3[j][0..1] -> row m1+gid,   cols 8j+2tig..+1
        //        c3[j][2..3] -> row m1+gid+8, cols 8j+2tig..+1
        float* outA = comp + (row0 + m1 + gid) * DIM + 2 * tig;
        float* outB = comp + (row0 + m1 + gid + 8) * DIM + 2 * tig;
#pragma unroll
        for (int j = 0; j < 8; j++) {
            *(float2*)(outA + 8 * j) = make_float2(c3[j][0], c3[j][1]);
            *(float2*)(outB + 8 * j) = make_float2(c3[j][2], c3[j][3]);
        }
    }
}

// ---------------- launch ----------------
extern "C" void kernel_launch(void* const* d_in, const int* in_sizes, int n_in,
                              void* d_out, int out_size) {
    const float* W  = (const float*)d_in[0];
    const float* C0 = (const float*)d_in[1];
    float* out  = (float*)d_out;
    float* comp = out;                                    // [N, D]
    float* clus = out + (size_t)NROWS * DIM;              // [K, D]
    float* attn = clus + (size_t)KC * DIM;                // [N, K]

    int sms = 0;
    cudaDeviceGetAttribute(&sms, cudaDevAttrMultiProcessorCount, 0);
    if (sms <= 0 || sms > MAXGRID) sms = MAXGRID;
    const int grid_iter = 2 * sms;                        // 2 CTAs/SM, bid%SMs pairing

    const int smem_iter  = 23744 * (int)sizeof(float);    // 94976 B  -> occ 2
    const int smem_final = 28864 * (int)sizeof(float);    // 115456 B -> occ 2
    cudaFuncSetAttribute(iter_fused, cudaFuncAttributeMaxDynamicSharedMemorySize, smem_iter);
    cudaFuncSetAttribute(final_fused, cudaFuncAttributeMaxDynamicSharedMemorySize, smem_final);

    init_kernel<<<NROWS / TPB, TPB>>>(W, C0);
    for (int it = 0; it < ITERS; it++)
        iter_fused<<<grid_iter, TPB, smem_iter>>>(it, W);
    final_fused<<<NROWS / MT, TPB, smem_final>>>(W, attn, comp, clus);
}